// round 11
// baseline (speedup 1.0000x reference)
#include <cuda_runtime.h>

#define NN 131072
#define DD 64
#define KK 512
#define ITERS 5
#define MROWS 128
#define NCHUNKS 4

#define FP_SCALE 1099511627776.0f          // 2^40
#define FP_INV   (1.0 / 1099511627776.0)   // 2^-40

// ---- smem layout (dynamic) ----
#define SM_A     0            // 64KB: A tf32 hi/lo frag layout [mt8][h2][s8][lane32][16B]
#define SM_BRAW  65536        // 2 x 34816B: raw fp32 B, 272B-padded rows (128 x (64f+4pad))
#define SM_C2    135168       // 512 f
#define SM_RB1   137216       // [2][128] f
#define SM_RB2   138240
#define SM_RI1   139264
#define SM_RI2   140288
#define SM_BIDX  141312       // [128] i
#define SMEM_REQ 141824

#define BROW 272              // padded raw B row stride (bytes)

// ---------------- scratch (device globals; no allocation allowed) ----------
__device__ __align__(256) float g_centers[KK * DD];
__device__ float g_c2[KK];
__device__ __align__(256) unsigned long long g_isums[KK * DD];
__device__ int   g_icounts[KK];
__device__ int   g_assign[NN];

// ---------------- helpers ----------------------------------------------------
__device__ __forceinline__ unsigned smem_u32(const void* p) {
    unsigned a;
    asm("{ .reg .u64 t; cvta.to.shared.u64 t, %1; cvt.u32.u64 %0, t; }"
        : "=r"(a) : "l"(p));
    return a;
}
__device__ __forceinline__ unsigned to_tf32(float x) {
    unsigned u;
    asm("cvt.rna.tf32.f32 %0, %1;" : "=r"(u) : "f"(x));
    return u;
}
__device__ __forceinline__ void sts128(unsigned a, unsigned x, unsigned y,
                                       unsigned z, unsigned w) {
    asm volatile("st.shared.v4.b32 [%0], {%1,%2,%3,%4};"
                 :: "r"(a), "r"(x), "r"(y), "r"(z), "r"(w) : "memory");
}
__device__ __forceinline__ void stsf32(unsigned a, float v) {
    asm volatile("st.shared.f32 [%0], %1;" :: "r"(a), "f"(v) : "memory");
}
__device__ __forceinline__ void stsi32(unsigned a, int v) {
    asm volatile("st.shared.b32 [%0], %1;" :: "r"(a), "r"(v) : "memory");
}
__device__ __forceinline__ float ldsf32(unsigned a) {
    float v; asm("ld.shared.f32 %0, [%1];" : "=f"(v) : "r"(a)); return v;
}
__device__ __forceinline__ int ldsi32(unsigned a) {
    int v; asm("ld.shared.b32 %0, [%1];" : "=r"(v) : "r"(a)); return v;
}
__device__ __forceinline__ uint4 lds128(unsigned a) {
    uint4 v;
    asm("ld.shared.v4.b32 {%0,%1,%2,%3}, [%4];"
        : "=r"(v.x), "=r"(v.y), "=r"(v.z), "=r"(v.w) : "r"(a));
    return v;
}
__device__ __forceinline__ float2 lds_f2(unsigned a) {
    float2 v;
    asm("ld.shared.v2.f32 {%0,%1}, [%2];" : "=f"(v.x), "=f"(v.y) : "r"(a));
    return v;
}
__device__ __forceinline__ void cp_async16(unsigned s, const void* g) {
    asm volatile("cp.async.cg.shared.global [%0], [%1], 16;\n" :: "r"(s), "l"(g));
}
__device__ __forceinline__ void cp_commit() {
    asm volatile("cp.async.commit_group;\n");
}
__device__ __forceinline__ void cp_wait1() {
    asm volatile("cp.async.wait_group 1;\n");
}
__device__ __forceinline__ void cp_wait0() {
    asm volatile("cp.async.wait_group 0;\n");
}
__device__ __forceinline__ void red_add_u64(unsigned long long* p, unsigned long long v) {
    asm volatile("red.global.add.u64 [%0], %1;\n" :: "l"(p), "l"(v) : "memory");
}
// tf32 tensor-core mma (PTX ISA sm_80+, valid on plain sm_103)
__device__ __forceinline__ void mma_tf32(float* c, uint4 a, uint2 b) {
    asm volatile(
        "mma.sync.aligned.m16n8k8.row.col.f32.tf32.tf32.f32 "
        "{%0,%1,%2,%3}, {%4,%5,%6,%7}, {%8,%9}, {%0,%1,%2,%3};"
        : "+f"(c[0]), "+f"(c[1]), "+f"(c[2]), "+f"(c[3])
        : "r"(a.x), "r"(a.y), "r"(a.z), "r"(a.w), "r"(b.x), "r"(b.y));
}
__device__ __forceinline__ void top2_update(float& b1, int& i1, float& b2, int& i2,
                                            float m, int idx) {
    if (m < b1)      { b2 = b1; i2 = i1; b1 = m; i1 = idx; }
    else if (m < b2) { b2 = m;  i2 = idx; }
}

// ---------------- prep: zero sums/counts, c2 of initial centers ------------
__global__ void prep_kernel(const float* __restrict__ centers0) {
    int k = blockIdx.x;
    int d = threadIdx.x;
    float v = centers0[k * DD + d];
    g_isums[k * DD + d] = 0ULL;
    if (d == 0) g_icounts[k] = 0;

    float s = __fmul_rn(v, v);
    #pragma unroll
    for (int o = 16; o > 0; o >>= 1) s += __shfl_down_sync(0xffffffffu, s, o);
    __shared__ float sh[2];
    if ((d & 31) == 0) sh[d >> 5] = s;
    __syncthreads();
    if (d == 0) g_c2[k] = __fadd_rn(sh[0], sh[1]);
}

// ---------------- assign: tf32 3-product split GEMM on tensor cores --------
__global__ __launch_bounds__(256) void assign_kernel(
    const float* __restrict__ X,
    const float* __restrict__ centers0,
    int iter)
{
    const float* __restrict__ C = (iter == 0) ? centers0 : g_centers;

    extern __shared__ __align__(16) char smem_raw[];
    const unsigned base = smem_u32(smem_raw);
    const unsigned Ab  = base + SM_A;
    const unsigned Rb  = base + SM_BRAW;
    const unsigned C2b = base + SM_C2;

    const int tid = threadIdx.x;
    const int l = tid & 31, w = tid >> 5;
    const int wm = w & 3, wn = w >> 2;
    const int g = l >> 2, q = l & 3;

    const float* Xg = X + (size_t)blockIdx.x * MROWS * DD;

    // ---- issue cp.async for raw B chunks 0,1 FIRST (overlaps A staging) ----
    #pragma unroll
    for (int c0 = 0; c0 < 2; c0++) {
        const char* src = (const char*)(C + (size_t)c0 * 128 * DD);
        unsigned dstb = Rb + (unsigned)c0 * 34816u;
        #pragma unroll
        for (int k = 0; k < 8; k++) {
            int id = tid + k * 256;
            int row = id >> 4, ch = id & 15;
            cp_async16(dstb + row * BROW + ch * 16, src + row * 256 + ch * 16);
        }
        cp_commit();
    }

    // ---- c2 -> smem ----
    #pragma unroll
    for (int i = 0; i < 2; i++)
        stsf32(C2b + (tid + i * 256) * 4, g_c2[tid + i * 256]);

    // ---- stage A (tf32 hi/lo, frag layout; warp w covers kstep s=w) ----
    {
        const int k = 8 * w + q;
        #pragma unroll
        for (int mt = 0; mt < 8; mt++) {
            const int r0 = mt * 16 + g;
            float x00 = Xg[r0 * DD + k];
            float x10 = Xg[(r0 + 8) * DD + k];
            float x01 = Xg[r0 * DD + k + 4];
            float x11 = Xg[(r0 + 8) * DD + k + 4];
            unsigned h00 = to_tf32(x00), h10 = to_tf32(x10);
            unsigned h01 = to_tf32(x01), h11 = to_tf32(x11);
            unsigned o00 = to_tf32(__fsub_rn(x00, __uint_as_float(h00)));
            unsigned o10 = to_tf32(__fsub_rn(x10, __uint_as_float(h10)));
            unsigned o01 = to_tf32(__fsub_rn(x01, __uint_as_float(h01)));
            unsigned o11 = to_tf32(__fsub_rn(x11, __uint_as_float(h11)));
            sts128(Ab + mt * 8192 + w * 512 + l * 16, h00, h10, h01, h11);
            sts128(Ab + mt * 8192 + 4096 + w * 512 + l * 16, o00, o10, o01, o11);
        }
    }
    __syncthreads();

    float b1v[2][2], b2v[2][2];
    int   i1v[2][2], i2v[2][2];
    #pragma unroll
    for (int mi = 0; mi < 2; mi++)
        #pragma unroll
        for (int u = 0; u < 2; u++) {
            b1v[mi][u] = 3.4e38f; b2v[mi][u] = 3.4e38f;
            i1v[mi][u] = 0;       i2v[mi][u] = 0;
        }

    for (int c = 0; c < NCHUNKS; c++) {
        if (c == NCHUNKS - 1) cp_wait0(); else cp_wait1();
        __syncthreads();
        const unsigned rawb = Rb + (unsigned)(c & 1) * 34816u;

        float acc[2][8][4];
        #pragma unroll
        for (int mi = 0; mi < 2; mi++)
            #pragma unroll
            for (int nt = 0; nt < 8; nt++)
                #pragma unroll
                for (int j = 0; j < 4; j++) acc[mi][nt][j] = 0.0f;

        #pragma unroll 2
        for (int s = 0; s < 8; s++) {
            uint4 ahi[2], alo[2];
            #pragma unroll
            for (int mi = 0; mi < 2; mi++) {
                ahi[mi] = lds128(Ab + (2 * wm + mi) * 8192 + s * 512 + l * 16);
                alo[mi] = lds128(Ab + (2 * wm + mi) * 8192 + 4096 + s * 512 + l * 16);
            }
            #pragma unroll
            for (int nt = 0; nt < 8; nt++) {
                // raw B values for this frag: center (8wn+nt)*8+g, d = 8s+q, 8s+q+4
                unsigned addr = rawb + (unsigned)(((8 * wn + nt) * 8 + g) * BROW
                                                 + (8 * s + q) * 4);
                float r0 = ldsf32(addr);
                float r1 = ldsf32(addr + 16);
                unsigned h0 = to_tf32(r0), h1 = to_tf32(r1);
                unsigned o0 = to_tf32(__fsub_rn(r0, __uint_as_float(h0)));
                unsigned o1 = to_tf32(__fsub_rn(r1, __uint_as_float(h1)));
                uint2 bhi = {h0, h1}, blo = {o0, o1};
                #pragma unroll
                for (int mi = 0; mi < 2; mi++) {
                    mma_tf32(acc[mi][nt], ahi[mi], bhi);   // hi*hi
                    mma_tf32(acc[mi][nt], ahi[mi], blo);   // hi*lo
                    mma_tf32(acc[mi][nt], alo[mi], bhi);   // lo*hi
                }
            }
        }

        // candidates: metric = c2 - 2*dot (x2 constant per row)
        #pragma unroll
        for (int nt = 0; nt < 8; nt++) {
            const int colb = c * 128 + (8 * wn + nt) * 8 + 2 * q;
            float2 cc = lds_f2(C2b + colb * 4);
            #pragma unroll
            for (int mi = 0; mi < 2; mi++)
                #pragma unroll
                for (int u = 0; u < 2; u++) {
                    float m0 = __fsub_rn(cc.x, __fmul_rn(2.0f, acc[mi][nt][u * 2 + 0]));
                    float m1 = __fsub_rn(cc.y, __fmul_rn(2.0f, acc[mi][nt][u * 2 + 1]));
                    top2_update(b1v[mi][u], i1v[mi][u], b2v[mi][u], i2v[mi][u], m0, colb);
                    top2_update(b1v[mi][u], i1v[mi][u], b2v[mi][u], i2v[mi][u], m1, colb + 1);
                }
        }
        __syncthreads();

        if (c + 2 < NCHUNKS) {
            const char* src = (const char*)(C + (size_t)(c + 2) * 128 * DD);
            unsigned dstb = Rb + (unsigned)(c & 1) * 34816u;
            #pragma unroll
            for (int k = 0; k < 8; k++) {
                int id = tid + k * 256;
                int row = id >> 4, ch = id & 15;
                cp_async16(dstb + row * BROW + ch * 16, src + row * 256 + ch * 16);
            }
            cp_commit();
        }
    }

    // ---- cross-lane top2 merge within 4-lane groups (same rows) ----
    #pragma unroll
    for (int mi = 0; mi < 2; mi++)
        #pragma unroll
        for (int u = 0; u < 2; u++) {
            float B1 = b1v[mi][u], B2 = b2v[mi][u];
            int   I1 = i1v[mi][u], I2 = i2v[mi][u];
            #pragma unroll
            for (int off = 1; off <= 2; off <<= 1) {
                float oB1 = __shfl_xor_sync(0xffffffffu, B1, off);
                int   oI1 = __shfl_xor_sync(0xffffffffu, I1, off);
                float oB2 = __shfl_xor_sync(0xffffffffu, B2, off);
                int   oI2 = __shfl_xor_sync(0xffffffffu, I2, off);
                if (oB1 < B1 || (oB1 == B1 && oI1 < I1)) {
                    if (B1 < oB2 || (B1 == oB2 && I1 < oI2)) { B2 = B1; I2 = I1; }
                    else { B2 = oB2; I2 = oI2; }
                    B1 = oB1; I1 = oI1;
                } else {
                    if (oB1 < B2) { B2 = oB1; I2 = oI1; }
                }
            }
            if (q == 0) {
                int row = (2 * wm + mi) * 16 + u * 8 + g;
                stsf32(base + SM_RB1 + (wn * 128 + row) * 4, B1);
                stsf32(base + SM_RB2 + (wn * 128 + row) * 4, B2);
                stsi32(base + SM_RI1 + (wn * 128 + row) * 4, I1);
                stsi32(base + SM_RI2 + (wn * 128 + row) * 4, I2);
            }
        }
    __syncthreads();

    // ---- per-row final merge + near-tie EXACT full rescan ----
    if (tid < MROWS) {
        int row = tid;
        float B1 = ldsf32(base + SM_RB1 + row * 4);
        float B2 = ldsf32(base + SM_RB2 + row * 4);
        int   I1 = ldsi32(base + SM_RI1 + row * 4);
        float oB1 = ldsf32(base + SM_RB1 + (128 + row) * 4);
        float oB2 = ldsf32(base + SM_RB2 + (128 + row) * 4);
        int   oI1 = ldsi32(base + SM_RI1 + (128 + row) * 4);
        if (oB1 < B1) {
            if (B1 < oB2) B2 = B1;
            else          B2 = oB2;
            B1 = oB1; I1 = oI1;
        } else {
            if (oB1 < B2) B2 = oB1;
        }

        int bi = I1;
        if (B2 - B1 < 1e-3f) {
            // exact deterministic fp32 rescan over all 512 centers
            const float* xr = Xg + row * DD;
            float x2 = 0.0f;
            #pragma unroll
            for (int d = 0; d < DD; d++) x2 = __fmaf_rn(xr[d], xr[d], x2);
            float bb = 3.4e38f;
            int   ib = 0;
            for (int kc = 0; kc < KK; kc++) {
                const float* cr = C + (size_t)kc * DD;
                float d0 = 0.0f, d1 = 0.0f, d2a = 0.0f, d3 = 0.0f;
                #pragma unroll
                for (int d = 0; d < DD; d += 4) {
                    d0 = __fmaf_rn(xr[d],     cr[d],     d0);
                    d1 = __fmaf_rn(xr[d + 1], cr[d + 1], d1);
                    d2a= __fmaf_rn(xr[d + 2], cr[d + 2], d2a);
                    d3 = __fmaf_rn(xr[d + 3], cr[d + 3], d3);
                }
                float dot = __fadd_rn(__fadd_rn(d0, d1), __fadd_rn(d2a, d3));
                float cc  = ldsf32(C2b + kc * 4);
                float dd  = __fsub_rn(__fadd_rn(x2, cc), __fmul_rn(2.0f, dot));
                if (dd < bb) { bb = dd; ib = kc; }
            }
            bi = ib;
        }
        stsi32(base + SM_BIDX + row * 4, bi);
        g_assign[blockIdx.x * MROWS + row] = bi;
        atomicAdd(&g_icounts[bi], 1);
    }
    __syncthreads();

    // ---- deterministic fixed-point sums (2 threads/row) ----
    {
        int row = tid >> 1, half = tid & 1;
        int bi = ldsi32(base + SM_BIDX + row * 4);
        const float4* xr = (const float4*)(Xg + row * DD + half * 32);
        unsigned long long* s = &g_isums[(size_t)bi * DD + half * 32];
        #pragma unroll
        for (int qq = 0; qq < 8; qq++) {
            float4 v = xr[qq];
            red_add_u64(&s[qq * 4 + 0], (unsigned long long)llrintf(v.x * FP_SCALE));
            red_add_u64(&s[qq * 4 + 1], (unsigned long long)llrintf(v.y * FP_SCALE));
            red_add_u64(&s[qq * 4 + 2], (unsigned long long)llrintf(v.z * FP_SCALE));
            red_add_u64(&s[qq * 4 + 3], (unsigned long long)llrintf(v.w * FP_SCALE));
        }
    }
}

// ---------------- centers update (+ c2, + reset sums/counts) ---------------
__global__ void update_kernel(const float* __restrict__ X,
                              const int* __restrict__ repl,
                              int iter)
{
    int k = blockIdx.x;
    int d = threadIdx.x;
    int icnt = g_icounts[k];
    long long ll = (long long)g_isums[k * DD + d];
    float s   = (float)((double)ll * FP_INV);
    float cnt = (float)icnt;
    float v   = __fdiv_rn(s, fmaxf(cnt, 1.0f));
    if (v == 0.0f) {
        int r = repl[iter * KK + k];
        v = X[(size_t)r * DD + d];
    }
    g_centers[k * DD + d] = v;
    g_isums[k * DD + d] = 0ULL;
    if (d == 0) g_icounts[k] = 0;

    float sq = __fmul_rn(v, v);
    #pragma unroll
    for (int o = 16; o > 0; o >>= 1) sq += __shfl_down_sync(0xffffffffu, sq, o);
    __shared__ float sh[2];
    if ((d & 31) == 0) sh[d >> 5] = sq;
    __syncthreads();
    if (d == 0) g_c2[k] = __fadd_rn(sh[0], sh[1]);
}

// ---------------- output: [assignments as float | centers] -----------------
__global__ void out_kernel(float* __restrict__ out) {
    int i = blockIdx.x * blockDim.x + threadIdx.x;
    if (i < NN) {
        out[i] = (float)g_assign[i];
    } else if (i < NN + KK * DD) {
        out[i] = g_centers[i - NN];
    }
}

// ---------------- launch ----------------------------------------------------
extern "C" void kernel_launch(void* const* d_in, const int* in_sizes, int n_in,
                              void* d_out, int out_size)
{
    const float* X    = nullptr;
    const float* C0   = nullptr;
    const int*   repl = nullptr;
    for (int i = 0; i < n_in; i++) {
        if (in_sizes[i] == NN * DD)       X    = (const float*)d_in[i];
        else if (in_sizes[i] == KK * DD)  C0   = (const float*)d_in[i];
        else if (in_sizes[i] == ITERS*KK) repl = (const int*)d_in[i];
    }
    float* out = (float*)d_out;

    cudaFuncSetAttribute(assign_kernel,
                         cudaFuncAttributeMaxDynamicSharedMemorySize, SMEM_REQ);

    prep_kernel<<<KK, DD>>>(C0);
    for (int i = 0; i < ITERS; i++) {
        assign_kernel<<<NN / MROWS, 256, SMEM_REQ>>>(X, C0, i);
        update_kernel<<<KK, DD>>>(X, repl, i);
    }
    int total = NN + KK * DD;
    out_kernel<<<(total + 255) / 256, 256>>>(out);
}

// round 12
// speedup vs baseline: 1.0474x; 1.0474x over previous
#include <cuda_runtime.h>

#define NN 131072
#define DD 64
#define KK 512
#define ITERS 5
#define MROWS 128
#define NCHUNKS 4

#define FP_SCALE 1099511627776.0f          // 2^40
#define FP_INV   (1.0 / 1099511627776.0)   // 2^-40

// ---- smem layout (dynamic) ----
#define SM_A     0            // 64KB: A tf32 hi/lo frag layout [mt8][h2][s8][lane32][16B]
#define SM_B     65536        // 2 x 64KB: frag-ready B [nt16][s8][lane32][16B {h0,h1,o0,o1}]
#define SM_C2    196608       // 512 f
#define SM_RB1   198656       // [2][128] f
#define SM_RB2   199680
#define SM_RI1   200704
#define SM_RI2   201728
#define SM_BIDX  202752       // [128] i
#define SMEM_REQ 203264

// ---------------- scratch (device globals; no allocation allowed) ----------
__device__ __align__(256) float g_centers[KK * DD];
__device__ float g_c2[KK];
__device__ __align__(256) unsigned long long g_isums[KK * DD];
__device__ int   g_icounts[KK];
__device__ int   g_assign[NN];
// frag-ready converted centers: [chunk4][nt16][s8][lane32] float4 {h0,h1,o0,o1}
__device__ __align__(256) float4 g_bcvt[NCHUNKS * 16 * 8 * 32];

// ---------------- helpers ----------------------------------------------------
__device__ __forceinline__ unsigned smem_u32(const void* p) {
    unsigned a;
    asm("{ .reg .u64 t; cvta.to.shared.u64 t, %1; cvt.u32.u64 %0, t; }"
        : "=r"(a) : "l"(p));
    return a;
}
__device__ __forceinline__ unsigned to_tf32(float x) {
    unsigned u;
    asm("cvt.rna.tf32.f32 %0, %1;" : "=r"(u) : "f"(x));
    return u;
}
__device__ __forceinline__ void sts128(unsigned a, unsigned x, unsigned y,
                                       unsigned z, unsigned w) {
    asm volatile("st.shared.v4.b32 [%0], {%1,%2,%3,%4};"
                 :: "r"(a), "r"(x), "r"(y), "r"(z), "r"(w) : "memory");
}
__device__ __forceinline__ void stsf32(unsigned a, float v) {
    asm volatile("st.shared.f32 [%0], %1;" :: "r"(a), "f"(v) : "memory");
}
__device__ __forceinline__ void stsi32(unsigned a, int v) {
    asm volatile("st.shared.b32 [%0], %1;" :: "r"(a), "r"(v) : "memory");
}
__device__ __forceinline__ float ldsf32(unsigned a) {
    float v; asm("ld.shared.f32 %0, [%1];" : "=f"(v) : "r"(a)); return v;
}
__device__ __forceinline__ int ldsi32(unsigned a) {
    int v; asm("ld.shared.b32 %0, [%1];" : "=r"(v) : "r"(a)); return v;
}
__device__ __forceinline__ uint4 lds128(unsigned a) {
    uint4 v;
    asm("ld.shared.v4.b32 {%0,%1,%2,%3}, [%4];"
        : "=r"(v.x), "=r"(v.y), "=r"(v.z), "=r"(v.w) : "r"(a));
    return v;
}
__device__ __forceinline__ float2 lds_f2(unsigned a) {
    float2 v;
    asm("ld.shared.v2.f32 {%0,%1}, [%2];" : "=f"(v.x), "=f"(v.y) : "r"(a));
    return v;
}
__device__ __forceinline__ void cp_async16(unsigned s, const void* g) {
    asm volatile("cp.async.cg.shared.global [%0], [%1], 16;\n" :: "r"(s), "l"(g));
}
__device__ __forceinline__ void cp_commit() {
    asm volatile("cp.async.commit_group;\n");
}
__device__ __forceinline__ void cp_wait1() {
    asm volatile("cp.async.wait_group 1;\n");
}
__device__ __forceinline__ void cp_wait0() {
    asm volatile("cp.async.wait_group 0;\n");
}
__device__ __forceinline__ void red_add_u64(unsigned long long* p, unsigned long long v) {
    asm volatile("red.global.add.u64 [%0], %1;\n" :: "l"(p), "l"(v) : "memory");
}
// tf32 tensor-core mma (PTX ISA sm_80+, valid on plain sm_103)
__device__ __forceinline__ void mma_tf32(float* c, uint4 a, unsigned b0, unsigned b1) {
    asm volatile(
        "mma.sync.aligned.m16n8k8.row.col.f32.tf32.tf32.f32 "
        "{%0,%1,%2,%3}, {%4,%5,%6,%7}, {%8,%9}, {%0,%1,%2,%3};"
        : "+f"(c[0]), "+f"(c[1]), "+f"(c[2]), "+f"(c[3])
        : "r"(a.x), "r"(a.y), "r"(a.z), "r"(a.w), "r"(b0), "r"(b1));
}
__device__ __forceinline__ void top2_update(float& b1, int& i1, float& b2, int& i2,
                                            float m, int idx) {
    if (m < b1)      { b2 = b1; i2 = i1; b1 = m; i1 = idx; }
    else if (m < b2) { b2 = m;  i2 = idx; }
}

// ---------------- prep: zero sums/counts, c2 of initial centers ------------
__global__ void prep_kernel(const float* __restrict__ centers0) {
    int k = blockIdx.x;
    int d = threadIdx.x;
    float v = centers0[k * DD + d];
    g_isums[k * DD + d] = 0ULL;
    if (d == 0) g_icounts[k] = 0;

    float s = __fmul_rn(v, v);
    #pragma unroll
    for (int o = 16; o > 0; o >>= 1) s += __shfl_down_sync(0xffffffffu, s, o);
    __shared__ float sh[2];
    if ((d & 31) == 0) sh[d >> 5] = s;
    __syncthreads();
    if (d == 0) g_c2[k] = __fadd_rn(sh[0], sh[1]);
}

// ---------------- bconv: centers -> frag-ready tf32 hi/lo global buffer -----
// work item = (gc, s, q): 512*8*4 = 16384 threads
__global__ void bconv_kernel(const float* __restrict__ centers0, int iter) {
    const float* __restrict__ C = (iter == 0) ? centers0 : g_centers;
    int idx = blockIdx.x * blockDim.x + threadIdx.x;   // 0..16383
    int gc = idx >> 5;
    int rem = idx & 31;
    int s = rem >> 2, q = rem & 3;

    float v0 = C[gc * DD + 8 * s + q];
    float v1 = C[gc * DD + 8 * s + q + 4];
    unsigned h0 = to_tf32(v0), h1 = to_tf32(v1);
    unsigned o0 = to_tf32(__fsub_rn(v0, __uint_as_float(h0)));
    unsigned o1 = to_tf32(__fsub_rn(v1, __uint_as_float(h1)));

    int c  = gc >> 7;
    int np = gc & 127;
    int nt = np >> 3, g = np & 7;
    int l  = g * 4 + q;
    // float4 index: [c][nt][s][l]
    g_bcvt[((c * 16 + nt) * 8 + s) * 32 + l] =
        make_float4(__uint_as_float(h0), __uint_as_float(h1),
                    __uint_as_float(o0), __uint_as_float(o1));
}

// ---------------- assign: tf32 3-product split GEMM on tensor cores --------
__global__ __launch_bounds__(256) void assign_kernel(
    const float* __restrict__ X,
    const float* __restrict__ centers0,
    int iter)
{
    const float* __restrict__ C = (iter == 0) ? centers0 : g_centers;

    extern __shared__ __align__(16) char smem_raw[];
    const unsigned base = smem_u32(smem_raw);
    const unsigned Ab  = base + SM_A;
    const unsigned Bb  = base + SM_B;
    const unsigned C2b = base + SM_C2;

    const int tid = threadIdx.x;
    const int l = tid & 31, w = tid >> 5;
    const int wm = w & 3, wn = w >> 2;
    const int g = l >> 2, q = l & 3;

    const float* Xg = X + (size_t)blockIdx.x * MROWS * DD;

    // ---- cp.async frag-ready B chunks 0,1 (64KB each, linear) ----
    #pragma unroll
    for (int c0 = 0; c0 < 2; c0++) {
        const char* src = (const char*)&g_bcvt[c0 * 4096];
        unsigned dstb = Bb + (unsigned)c0 * 65536u;
        #pragma unroll
        for (int k = 0; k < 16; k++)
            cp_async16(dstb + tid * 16 + k * 4096, src + tid * 16 + k * 4096);
        cp_commit();
    }

    // ---- c2 -> smem ----
    #pragma unroll
    for (int i = 0; i < 2; i++)
        stsf32(C2b + (tid + i * 256) * 4, g_c2[tid + i * 256]);

    // ---- stage A (tf32 hi/lo, frag layout; warp w covers kstep s=w) ----
    {
        const int k = 8 * w + q;
        #pragma unroll
        for (int mt = 0; mt < 8; mt++) {
            const int r0 = mt * 16 + g;
            float x00 = Xg[r0 * DD + k];
            float x10 = Xg[(r0 + 8) * DD + k];
            float x01 = Xg[r0 * DD + k + 4];
            float x11 = Xg[(r0 + 8) * DD + k + 4];
            unsigned h00 = to_tf32(x00), h10 = to_tf32(x10);
            unsigned h01 = to_tf32(x01), h11 = to_tf32(x11);
            unsigned o00 = to_tf32(__fsub_rn(x00, __uint_as_float(h00)));
            unsigned o10 = to_tf32(__fsub_rn(x10, __uint_as_float(h10)));
            unsigned o01 = to_tf32(__fsub_rn(x01, __uint_as_float(h01)));
            unsigned o11 = to_tf32(__fsub_rn(x11, __uint_as_float(h11)));
            sts128(Ab + mt * 8192 + w * 512 + l * 16, h00, h10, h01, h11);
            sts128(Ab + mt * 8192 + 4096 + w * 512 + l * 16, o00, o10, o01, o11);
        }
    }
    __syncthreads();

    float b1v[2][2], b2v[2][2];
    int   i1v[2][2], i2v[2][2];
    #pragma unroll
    for (int mi = 0; mi < 2; mi++)
        #pragma unroll
        for (int u = 0; u < 2; u++) {
            b1v[mi][u] = 3.4e38f; b2v[mi][u] = 3.4e38f;
            i1v[mi][u] = 0;       i2v[mi][u] = 0;
        }

    for (int c = 0; c < NCHUNKS; c++) {
        if (c == NCHUNKS - 1) cp_wait0(); else cp_wait1();
        __syncthreads();
        const unsigned bufb = Bb + (unsigned)(c & 1) * 65536u;

        float acc[2][8][4];
        #pragma unroll
        for (int mi = 0; mi < 2; mi++)
            #pragma unroll
            for (int nt = 0; nt < 8; nt++)
                #pragma unroll
                for (int j = 0; j < 4; j++) acc[mi][nt][j] = 0.0f;

        #pragma unroll 2
        for (int s = 0; s < 8; s++) {
            uint4 ahi[2], alo[2];
            #pragma unroll
            for (int mi = 0; mi < 2; mi++) {
                ahi[mi] = lds128(Ab + (2 * wm + mi) * 8192 + s * 512 + l * 16);
                alo[mi] = lds128(Ab + (2 * wm + mi) * 8192 + 4096 + s * 512 + l * 16);
            }
            uint4 bf[8];
            #pragma unroll
            for (int nt = 0; nt < 8; nt++)
                bf[nt] = lds128(bufb + (8 * wn + nt) * 4096 + s * 512 + l * 16);
            #pragma unroll
            for (int nt = 0; nt < 8; nt++) {
                #pragma unroll
                for (int mi = 0; mi < 2; mi++) {
                    mma_tf32(acc[mi][nt], ahi[mi], bf[nt].x, bf[nt].y);  // hi*hi
                    mma_tf32(acc[mi][nt], ahi[mi], bf[nt].z, bf[nt].w);  // hi*lo
                    mma_tf32(acc[mi][nt], alo[mi], bf[nt].x, bf[nt].y);  // lo*hi
                }
            }
        }

        // candidates: metric = c2 - 2*dot (x2 constant per row)
        #pragma unroll
        for (int nt = 0; nt < 8; nt++) {
            const int colb = c * 128 + (8 * wn + nt) * 8 + 2 * q;
            float2 cc = lds_f2(C2b + colb * 4);
            #pragma unroll
            for (int mi = 0; mi < 2; mi++)
                #pragma unroll
                for (int u = 0; u < 2; u++) {
                    float m0 = __fsub_rn(cc.x, __fmul_rn(2.0f, acc[mi][nt][u * 2 + 0]));
                    float m1 = __fsub_rn(cc.y, __fmul_rn(2.0f, acc[mi][nt][u * 2 + 1]));
                    top2_update(b1v[mi][u], i1v[mi][u], b2v[mi][u], i2v[mi][u], m0, colb);
                    top2_update(b1v[mi][u], i1v[mi][u], b2v[mi][u], i2v[mi][u], m1, colb + 1);
                }
        }
        __syncthreads();

        if (c + 2 < NCHUNKS) {
            const char* src = (const char*)&g_bcvt[(c + 2) * 4096];
            unsigned dstb = Bb + (unsigned)(c & 1) * 65536u;
            #pragma unroll
            for (int k = 0; k < 16; k++)
                cp_async16(dstb + tid * 16 + k * 4096, src + tid * 16 + k * 4096);
            cp_commit();
        }
    }

    // ---- cross-lane top2 merge within 4-lane groups (same rows) ----
    #pragma unroll
    for (int mi = 0; mi < 2; mi++)
        #pragma unroll
        for (int u = 0; u < 2; u++) {
            float B1 = b1v[mi][u], B2 = b2v[mi][u];
            int   I1 = i1v[mi][u], I2 = i2v[mi][u];
            #pragma unroll
            for (int off = 1; off <= 2; off <<= 1) {
                float oB1 = __shfl_xor_sync(0xffffffffu, B1, off);
                int   oI1 = __shfl_xor_sync(0xffffffffu, I1, off);
                float oB2 = __shfl_xor_sync(0xffffffffu, B2, off);
                int   oI2 = __shfl_xor_sync(0xffffffffu, I2, off);
                if (oB1 < B1 || (oB1 == B1 && oI1 < I1)) {
                    if (B1 < oB2 || (B1 == oB2 && I1 < oI2)) { B2 = B1; I2 = I1; }
                    else { B2 = oB2; I2 = oI2; }
                    B1 = oB1; I1 = oI1;
                } else {
                    if (oB1 < B2) { B2 = oB1; I2 = oI1; }
                }
            }
            if (q == 0) {
                int row = (2 * wm + mi) * 16 + u * 8 + g;
                stsf32(base + SM_RB1 + (wn * 128 + row) * 4, B1);
                stsf32(base + SM_RB2 + (wn * 128 + row) * 4, B2);
                stsi32(base + SM_RI1 + (wn * 128 + row) * 4, I1);
                stsi32(base + SM_RI2 + (wn * 128 + row) * 4, I2);
            }
        }
    __syncthreads();

    // ---- per-row final merge + near-tie EXACT full rescan ----
    if (tid < MROWS) {
        int row = tid;
        float B1 = ldsf32(base + SM_RB1 + row * 4);
        float B2 = ldsf32(base + SM_RB2 + row * 4);
        int   I1 = ldsi32(base + SM_RI1 + row * 4);
        float oB1 = ldsf32(base + SM_RB1 + (128 + row) * 4);
        float oB2 = ldsf32(base + SM_RB2 + (128 + row) * 4);
        int   oI1 = ldsi32(base + SM_RI1 + (128 + row) * 4);
        if (oB1 < B1) {
            if (B1 < oB2) B2 = B1;
            else          B2 = oB2;
            B1 = oB1; I1 = oI1;
        } else {
            if (oB1 < B2) B2 = oB1;
        }

        int bi = I1;
        if (B2 - B1 < 1e-3f) {
            // exact deterministic fp32 rescan over all 512 centers
            const float* xr = Xg + row * DD;
            float x2 = 0.0f;
            #pragma unroll
            for (int d = 0; d < DD; d++) x2 = __fmaf_rn(xr[d], xr[d], x2);
            float bb = 3.4e38f;
            int   ib = 0;
            for (int kc = 0; kc < KK; kc++) {
                const float* cr = C + (size_t)kc * DD;
                float d0 = 0.0f, d1 = 0.0f, d2a = 0.0f, d3 = 0.0f;
                #pragma unroll
                for (int d = 0; d < DD; d += 4) {
                    d0 = __fmaf_rn(xr[d],     cr[d],     d0);
                    d1 = __fmaf_rn(xr[d + 1], cr[d + 1], d1);
                    d2a= __fmaf_rn(xr[d + 2], cr[d + 2], d2a);
                    d3 = __fmaf_rn(xr[d + 3], cr[d + 3], d3);
                }
                float dot = __fadd_rn(__fadd_rn(d0, d1), __fadd_rn(d2a, d3));
                float cc  = ldsf32(C2b + kc * 4);
                float dd  = __fsub_rn(__fadd_rn(x2, cc), __fmul_rn(2.0f, dot));
                if (dd < bb) { bb = dd; ib = kc; }
            }
            bi = ib;
        }
        stsi32(base + SM_BIDX + row * 4, bi);
        g_assign[blockIdx.x * MROWS + row] = bi;
        atomicAdd(&g_icounts[bi], 1);
    }
    __syncthreads();

    // ---- deterministic fixed-point sums (2 threads/row) ----
    {
        int row = tid >> 1, half = tid & 1;
        int bi = ldsi32(base + SM_BIDX + row * 4);
        const float4* xr = (const float4*)(Xg + row * DD + half * 32);
        unsigned long long* s = &g_isums[(size_t)bi * DD + half * 32];
        #pragma unroll
        for (int qq = 0; qq < 8; qq++) {
            float4 v = xr[qq];
            red_add_u64(&s[qq * 4 + 0], (unsigned long long)llrintf(v.x * FP_SCALE));
            red_add_u64(&s[qq * 4 + 1], (unsigned long long)llrintf(v.y * FP_SCALE));
            red_add_u64(&s[qq * 4 + 2], (unsigned long long)llrintf(v.z * FP_SCALE));
            red_add_u64(&s[qq * 4 + 3], (unsigned long long)llrintf(v.w * FP_SCALE));
        }
    }
}

// ---------------- centers update (+ c2, + reset sums/counts) ---------------
__global__ void update_kernel(const float* __restrict__ X,
                              const int* __restrict__ repl,
                              int iter)
{
    int k = blockIdx.x;
    int d = threadIdx.x;
    int icnt = g_icounts[k];
    long long ll = (long long)g_isums[k * DD + d];
    float s   = (float)((double)ll * FP_INV);
    float cnt = (float)icnt;
    float v   = __fdiv_rn(s, fmaxf(cnt, 1.0f));
    if (v == 0.0f) {
        int r = repl[iter * KK + k];
        v = X[(size_t)r * DD + d];
    }
    g_centers[k * DD + d] = v;
    g_isums[k * DD + d] = 0ULL;
    if (d == 0) g_icounts[k] = 0;

    float sq = __fmul_rn(v, v);
    #pragma unroll
    for (int o = 16; o > 0; o >>= 1) sq += __shfl_down_sync(0xffffffffu, sq, o);
    __shared__ float sh[2];
    if ((d & 31) == 0) sh[d >> 5] = sq;
    __syncthreads();
    if (d == 0) g_c2[k] = __fadd_rn(sh[0], sh[1]);
}

// ---------------- output: [assignments as float | centers] -----------------
__global__ void out_kernel(float* __restrict__ out) {
    int i = blockIdx.x * blockDim.x + threadIdx.x;
    if (i < NN) {
        out[i] = (float)g_assign[i];
    } else if (i < NN + KK * DD) {
        out[i] = g_centers[i - NN];
    }
}

// ---------------- launch ----------------------------------------------------
extern "C" void kernel_launch(void* const* d_in, const int* in_sizes, int n_in,
                              void* d_out, int out_size)
{
    const float* X    = nullptr;
    const float* C0   = nullptr;
    const int*   repl = nullptr;
    for (int i = 0; i < n_in; i++) {
        if (in_sizes[i] == NN * DD)       X    = (const float*)d_in[i];
        else if (in_sizes[i] == KK * DD)  C0   = (const float*)d_in[i];
        else if (in_sizes[i] == ITERS*KK) repl = (const int*)d_in[i];
    }
    float* out = (float*)d_out;

    cudaFuncSetAttribute(assign_kernel,
                         cudaFuncAttributeMaxDynamicSharedMemorySize, SMEM_REQ);

    prep_kernel<<<KK, DD>>>(C0);
    for (int i = 0; i < ITERS; i++) {
        bconv_kernel<<<64, 256>>>(C0, i);
        assign_kernel<<<NN / MROWS, 256, SMEM_REQ>>>(X, C0, i);
        update_kernel<<<KK, DD>>>(X, repl, i);
    }
    int total = NN + KK * DD;
    out_kernel<<<(total + 255) / 256, 256>>>(out);
}

// round 13
// speedup vs baseline: 1.3294x; 1.2692x over previous
#include <cuda_runtime.h>
#include <cuda_bf16.h>

#define NN 131072
#define DD 64
#define KK 512
#define ITERS 5
#define MROWS 128
#define NCHUNKS 4

#define FP_SCALE 1099511627776.0f          // 2^40
#define FP_INV   (1.0 / 1099511627776.0)   // 2^-40

// ---- smem layout (dynamic) ----
#define SM_A     0            // 32KB: A bf16 hi/lo frags [mt8][h2][s4][lane32][16B]
#define SM_B     32768        // 2 x 32KB: B frags [nt16][s4][lane32][16B {hb0,hb1,lb0,lb1}]
#define SM_C2    98304        // 512 f
#define SM_RB1   100352       // [2][128] f
#define SM_RB2   101376
#define SM_RI1   102400
#define SM_RI2   103424
#define SM_BIDX  104448       // [128] i
#define SMEM_REQ 104960

// ---------------- scratch (device globals; no allocation allowed) ----------
__device__ __align__(256) float g_centers[KK * DD];
__device__ float g_c2[KK];
__device__ __align__(256) unsigned long long g_isums[KK * DD];
__device__ int   g_icounts[KK];
__device__ int   g_assign[NN];
// frag-ready bf16 hi/lo centers: [chunk4][nt16][s4][lane32] uint4 {hb0,hb1,lb0,lb1}
__device__ __align__(256) uint4 g_bcvt[NCHUNKS * 16 * 4 * 32];

// ---------------- helpers ----------------------------------------------------
__device__ __forceinline__ unsigned smem_u32(const void* p) {
    unsigned a;
    asm("{ .reg .u64 t; cvta.to.shared.u64 t, %1; cvt.u32.u64 %0, t; }"
        : "=r"(a) : "l"(p));
    return a;
}
__device__ __forceinline__ unsigned pack_hi(float a, float b) {
    unsigned ua = (unsigned)__bfloat16_as_ushort(__float2bfloat16(a));
    unsigned ub = (unsigned)__bfloat16_as_ushort(__float2bfloat16(b));
    return ua | (ub << 16);
}
__device__ __forceinline__ unsigned pack_lo(float a, float b) {
    float ah = __bfloat162float(__float2bfloat16(a));
    float bh = __bfloat162float(__float2bfloat16(b));
    return pack_hi(__fsub_rn(a, ah), __fsub_rn(b, bh));
}
__device__ __forceinline__ void sts128(unsigned a, unsigned x, unsigned y,
                                       unsigned z, unsigned w) {
    asm volatile("st.shared.v4.b32 [%0], {%1,%2,%3,%4};"
                 :: "r"(a), "r"(x), "r"(y), "r"(z), "r"(w) : "memory");
}
__device__ __forceinline__ void stsf32(unsigned a, float v) {
    asm volatile("st.shared.f32 [%0], %1;" :: "r"(a), "f"(v) : "memory");
}
__device__ __forceinline__ void stsi32(unsigned a, int v) {
    asm volatile("st.shared.b32 [%0], %1;" :: "r"(a), "r"(v) : "memory");
}
__device__ __forceinline__ float ldsf32(unsigned a) {
    float v; asm("ld.shared.f32 %0, [%1];" : "=f"(v) : "r"(a)); return v;
}
__device__ __forceinline__ int ldsi32(unsigned a) {
    int v; asm("ld.shared.b32 %0, [%1];" : "=r"(v) : "r"(a)); return v;
}
__device__ __forceinline__ uint4 lds128(unsigned a) {
    uint4 v;
    asm("ld.shared.v4.b32 {%0,%1,%2,%3}, [%4];"
        : "=r"(v.x), "=r"(v.y), "=r"(v.z), "=r"(v.w) : "r"(a));
    return v;
}
__device__ __forceinline__ float2 lds_f2(unsigned a) {
    float2 v;
    asm("ld.shared.v2.f32 {%0,%1}, [%2];" : "=f"(v.x), "=f"(v.y) : "r"(a));
    return v;
}
__device__ __forceinline__ void cp_async16(unsigned s, const void* g) {
    asm volatile("cp.async.cg.shared.global [%0], [%1], 16;\n" :: "r"(s), "l"(g));
}
__device__ __forceinline__ void cp_commit() {
    asm volatile("cp.async.commit_group;\n");
}
__device__ __forceinline__ void cp_wait1() {
    asm volatile("cp.async.wait_group 1;\n");
}
__device__ __forceinline__ void cp_wait0() {
    asm volatile("cp.async.wait_group 0;\n");
}
__device__ __forceinline__ void red_add_u64(unsigned long long* p, unsigned long long v) {
    asm volatile("red.global.add.u64 [%0], %1;\n" :: "l"(p), "l"(v) : "memory");
}
// bf16 tensor-core mma m16n8k16 (PTX ISA sm_80+, valid on plain sm_103)
__device__ __forceinline__ void mma_bf16(float* c, uint4 a, unsigned b0, unsigned b1) {
    asm volatile(
        "mma.sync.aligned.m16n8k16.row.col.f32.bf16.bf16.f32 "
        "{%0,%1,%2,%3}, {%4,%5,%6,%7}, {%8,%9}, {%0,%1,%2,%3};"
        : "+f"(c[0]), "+f"(c[1]), "+f"(c[2]), "+f"(c[3])
        : "r"(a.x), "r"(a.y), "r"(a.z), "r"(a.w), "r"(b0), "r"(b1));
}
__device__ __forceinline__ void top2_update(float& b1, int& i1, float& b2, int& i2,
                                            float m, int idx) {
    if (m < b1)      { b2 = b1; i2 = i1; b1 = m; i1 = idx; }
    else if (m < b2) { b2 = m;  i2 = idx; }
}

// ---------------- prep: zero sums/counts, c2 of initial centers ------------
__global__ void prep_kernel(const float* __restrict__ centers0) {
    int k = blockIdx.x;
    int d = threadIdx.x;
    float v = centers0[k * DD + d];
    g_isums[k * DD + d] = 0ULL;
    if (d == 0) g_icounts[k] = 0;

    float s = __fmul_rn(v, v);
    #pragma unroll
    for (int o = 16; o > 0; o >>= 1) s += __shfl_down_sync(0xffffffffu, s, o);
    __shared__ float sh[2];
    if ((d & 31) == 0) sh[d >> 5] = s;
    __syncthreads();
    if (d == 0) g_c2[k] = __fadd_rn(sh[0], sh[1]);
}

// ---------------- bconv: centers -> frag-ready bf16 hi/lo global buffer ----
// work item = (gc, s, q): 512*4*4 = 8192 threads
__global__ void bconv_kernel(const float* __restrict__ centers0, int iter) {
    const float* __restrict__ C = (iter == 0) ? centers0 : g_centers;
    int idx = blockIdx.x * blockDim.x + threadIdx.x;   // 0..8191
    int gc = idx >> 4;
    int rem = idx & 15;
    int s = rem >> 2, q = rem & 3;
    int k0 = 16 * s + 2 * q;

    const float* row = C + gc * DD;
    float v00 = row[k0],     v01 = row[k0 + 1];
    float v10 = row[k0 + 8], v11 = row[k0 + 9];
    unsigned hb0 = pack_hi(v00, v01), hb1 = pack_hi(v10, v11);
    unsigned lb0 = pack_lo(v00, v01), lb1 = pack_lo(v10, v11);

    int c  = gc >> 7;
    int np = gc & 127;
    int nt = np >> 3, g = np & 7;
    int l  = g * 4 + q;
    g_bcvt[((c * 16 + nt) * 4 + s) * 32 + l] = make_uint4(hb0, hb1, lb0, lb1);
}

// ---------------- assign: bf16 3-product split GEMM on tensor cores --------
__global__ __launch_bounds__(256, 2) void assign_kernel(
    const float* __restrict__ X,
    const float* __restrict__ centers0,
    int iter)
{
    const float* __restrict__ C = (iter == 0) ? centers0 : g_centers;

    extern __shared__ __align__(16) char smem_raw[];
    const unsigned base = smem_u32(smem_raw);
    const unsigned Ab  = base + SM_A;
    const unsigned Bb  = base + SM_B;
    const unsigned C2b = base + SM_C2;

    const int tid = threadIdx.x;
    const int l = tid & 31, w = tid >> 5;
    const int wm = w & 3, wn = w >> 2;
    const int g = l >> 2, q = l & 3;

    const float* Xg = X + (size_t)blockIdx.x * MROWS * DD;

    // ---- cp.async frag-ready B chunks 0,1 (32KB each) ----
    #pragma unroll
    for (int c0 = 0; c0 < 2; c0++) {
        const char* src = (const char*)&g_bcvt[c0 * 2048];
        unsigned dstb = Bb + (unsigned)c0 * 32768u;
        #pragma unroll
        for (int k = 0; k < 8; k++)
            cp_async16(dstb + tid * 16 + k * 4096, src + tid * 16 + k * 4096);
        cp_commit();
    }

    // ---- c2 -> smem ----
    #pragma unroll
    for (int i = 0; i < 2; i++)
        stsf32(C2b + (tid + i * 256) * 4, g_c2[tid + i * 256]);

    // ---- stage A (bf16 hi/lo frags; warp w: h = w>>2, s = w&3) ----
    {
        const int h = w >> 2, s = w & 3;
        const int k0 = 16 * s + 2 * q;
        #pragma unroll
        for (int mt = 0; mt < 8; mt++) {
            const float* r0p = Xg + (mt * 16 + g) * DD + k0;
            const float* r1p = r0p + 8 * DD;
            unsigned pa0, pa1, pa2, pa3;
            if (h == 0) {
                pa0 = pack_hi(r0p[0], r0p[1]);
                pa1 = pack_hi(r1p[0], r1p[1]);
                pa2 = pack_hi(r0p[8], r0p[9]);
                pa3 = pack_hi(r1p[8], r1p[9]);
            } else {
                pa0 = pack_lo(r0p[0], r0p[1]);
                pa1 = pack_lo(r1p[0], r1p[1]);
                pa2 = pack_lo(r0p[8], r0p[9]);
                pa3 = pack_lo(r1p[8], r1p[9]);
            }
            sts128(Ab + (((mt * 2 + h) * 4 + s) * 32 + l) * 16, pa0, pa1, pa2, pa3);
        }
    }
    __syncthreads();

    float b1v[2][2], b2v[2][2];
    int   i1v[2][2], i2v[2][2];
    #pragma unroll
    for (int mi = 0; mi < 2; mi++)
        #pragma unroll
        for (int u = 0; u < 2; u++) {
            b1v[mi][u] = 3.4e38f; b2v[mi][u] = 3.4e38f;
            i1v[mi][u] = 0;       i2v[mi][u] = 0;
        }

    for (int c = 0; c < NCHUNKS; c++) {
        if (c == NCHUNKS - 1) cp_wait0(); else cp_wait1();
        __syncthreads();
        const unsigned bufb = Bb + (unsigned)(c & 1) * 32768u;

        float acc[2][8][4];
        #pragma unroll
        for (int mi = 0; mi < 2; mi++)
            #pragma unroll
            for (int nt = 0; nt < 8; nt++)
                #pragma unroll
                for (int j = 0; j < 4; j++) acc[mi][nt][j] = 0.0f;

        #pragma unroll
        for (int s = 0; s < 4; s++) {
            uint4 ahi[2], alo[2];
            #pragma unroll
            for (int mi = 0; mi < 2; mi++) {
                ahi[mi] = lds128(Ab + ((((2 * wm + mi) * 2 + 0) * 4 + s) * 32 + l) * 16);
                alo[mi] = lds128(Ab + ((((2 * wm + mi) * 2 + 1) * 4 + s) * 32 + l) * 16);
            }
            uint4 bf[8];
            #pragma unroll
            for (int nt = 0; nt < 8; nt++)
                bf[nt] = lds128(bufb + (((8 * wn + nt) * 4 + s) * 32 + l) * 16);
            // product loops outermost: RAW distance 16 instr per accumulator
            #pragma unroll
            for (int nt = 0; nt < 8; nt++)
                #pragma unroll
                for (int mi = 0; mi < 2; mi++)
                    mma_bf16(acc[mi][nt], ahi[mi], bf[nt].x, bf[nt].y);  // hi*hi
            #pragma unroll
            for (int nt = 0; nt < 8; nt++)
                #pragma unroll
                for (int mi = 0; mi < 2; mi++)
                    mma_bf16(acc[mi][nt], ahi[mi], bf[nt].z, bf[nt].w);  // hi*lo
            #pragma unroll
            for (int nt = 0; nt < 8; nt++)
                #pragma unroll
                for (int mi = 0; mi < 2; mi++)
                    mma_bf16(acc[mi][nt], alo[mi], bf[nt].x, bf[nt].y);  // lo*hi
        }

        // candidates: metric = c2 - 2*dot (x2 constant per row)
        #pragma unroll
        for (int nt = 0; nt < 8; nt++) {
            const int colb = c * 128 + (8 * wn + nt) * 8 + 2 * q;
            float2 cc = lds_f2(C2b + colb * 4);
            #pragma unroll
            for (int mi = 0; mi < 2; mi++)
                #pragma unroll
                for (int u = 0; u < 2; u++) {
                    float m0 = __fsub_rn(cc.x, __fmul_rn(2.0f, acc[mi][nt][u * 2 + 0]));
                    float m1 = __fsub_rn(cc.y, __fmul_rn(2.0f, acc[mi][nt][u * 2 + 1]));
                    top2_update(b1v[mi][u], i1v[mi][u], b2v[mi][u], i2v[mi][u], m0, colb);
                    top2_update(b1v[mi][u], i1v[mi][u], b2v[mi][u], i2v[mi][u], m1, colb + 1);
                }
        }
        __syncthreads();

        if (c + 2 < NCHUNKS) {
            const char* src = (const char*)&g_bcvt[(c + 2) * 2048];
            unsigned dstb = Bb + (unsigned)(c & 1) * 32768u;
            #pragma unroll
            for (int k = 0; k < 8; k++)
                cp_async16(dstb + tid * 16 + k * 4096, src + tid * 16 + k * 4096);
            cp_commit();
        }
    }

    // ---- cross-lane top2 merge within 4-lane groups (same rows) ----
    #pragma unroll
    for (int mi = 0; mi < 2; mi++)
        #pragma unroll
        for (int u = 0; u < 2; u++) {
            float B1 = b1v[mi][u], B2 = b2v[mi][u];
            int   I1 = i1v[mi][u], I2 = i2v[mi][u];
            #pragma unroll
            for (int off = 1; off <= 2; off <<= 1) {
                float oB1 = __shfl_xor_sync(0xffffffffu, B1, off);
                int   oI1 = __shfl_xor_sync(0xffffffffu, I1, off);
                float oB2 = __shfl_xor_sync(0xffffffffu, B2, off);
                int   oI2 = __shfl_xor_sync(0xffffffffu, I2, off);
                if (oB1 < B1 || (oB1 == B1 && oI1 < I1)) {
                    if (B1 < oB2 || (B1 == oB2 && I1 < oI2)) { B2 = B1; I2 = I1; }
                    else { B2 = oB2; I2 = oI2; }
                    B1 = oB1; I1 = oI1;
                } else {
                    if (oB1 < B2) { B2 = oB1; I2 = oI1; }
                }
            }
            if (q == 0) {
                int row = (2 * wm + mi) * 16 + u * 8 + g;
                stsf32(base + SM_RB1 + (wn * 128 + row) * 4, B1);
                stsf32(base + SM_RB2 + (wn * 128 + row) * 4, B2);
                stsi32(base + SM_RI1 + (wn * 128 + row) * 4, I1);
                stsi32(base + SM_RI2 + (wn * 128 + row) * 4, I2);
            }
        }
    __syncthreads();

    // ---- per-row final merge + near-tie EXACT full rescan ----
    if (tid < MROWS) {
        int row = tid;
        float B1 = ldsf32(base + SM_RB1 + row * 4);
        float B2 = ldsf32(base + SM_RB2 + row * 4);
        int   I1 = ldsi32(base + SM_RI1 + row * 4);
        float oB1 = ldsf32(base + SM_RB1 + (128 + row) * 4);
        float oB2 = ldsf32(base + SM_RB2 + (128 + row) * 4);
        int   oI1 = ldsi32(base + SM_RI1 + (128 + row) * 4);
        if (oB1 < B1) {
            if (B1 < oB2) B2 = B1;
            else          B2 = oB2;
            B1 = oB1; I1 = oI1;
        } else {
            if (oB1 < B2) B2 = oB1;
        }

        int bi = I1;
        if (B2 - B1 < 1.5e-3f) {
            // exact deterministic fp32 rescan over all 512 centers
            const float* xr = Xg + row * DD;
            float x2 = 0.0f;
            #pragma unroll
            for (int d = 0; d < DD; d++) x2 = __fmaf_rn(xr[d], xr[d], x2);
            float bb = 3.4e38f;
            int   ib = 0;
            for (int kc = 0; kc < KK; kc++) {
                const float* cr = C + (size_t)kc * DD;
                float d0 = 0.0f, d1 = 0.0f, d2a = 0.0f, d3 = 0.0f;
                #pragma unroll
                for (int d = 0; d < DD; d += 4) {
                    d0 = __fmaf_rn(xr[d],     cr[d],     d0);
                    d1 = __fmaf_rn(xr[d + 1], cr[d + 1], d1);
                    d2a= __fmaf_rn(xr[d + 2], cr[d + 2], d2a);
                    d3 = __fmaf_rn(xr[d + 3], cr[d + 3], d3);
                }
                float dot = __fadd_rn(__fadd_rn(d0, d1), __fadd_rn(d2a, d3));
                float cc  = ldsf32(C2b + kc * 4);
                float dd  = __fsub_rn(__fadd_rn(x2, cc), __fmul_rn(2.0f, dot));
                if (dd < bb) { bb = dd; ib = kc; }
            }
            bi = ib;
        }
        stsi32(base + SM_BIDX + row * 4, bi);
        g_assign[blockIdx.x * MROWS + row] = bi;
        atomicAdd(&g_icounts[bi], 1);
    }
    __syncthreads();

    // ---- deterministic fixed-point sums (2 threads/row) ----
    {
        int row = tid >> 1, half = tid & 1;
        int bi = ldsi32(base + SM_BIDX + row * 4);
        const float4* xr = (const float4*)(Xg + row * DD + half * 32);
        unsigned long long* s = &g_isums[(size_t)bi * DD + half * 32];
        #pragma unroll
        for (int qq = 0; qq < 8; qq++) {
            float4 v = xr[qq];
            red_add_u64(&s[qq * 4 + 0], (unsigned long long)llrintf(v.x * FP_SCALE));
            red_add_u64(&s[qq * 4 + 1], (unsigned long long)llrintf(v.y * FP_SCALE));
            red_add_u64(&s[qq * 4 + 2], (unsigned long long)llrintf(v.z * FP_SCALE));
            red_add_u64(&s[qq * 4 + 3], (unsigned long long)llrintf(v.w * FP_SCALE));
        }
    }
}

// ---------------- centers update (+ c2, + reset sums/counts) ---------------
__global__ void update_kernel(const float* __restrict__ X,
                              const int* __restrict__ repl,
                              int iter)
{
    int k = blockIdx.x;
    int d = threadIdx.x;
    int icnt = g_icounts[k];
    long long ll = (long long)g_isums[k * DD + d];
    float s   = (float)((double)ll * FP_INV);
    float cnt = (float)icnt;
    float v   = __fdiv_rn(s, fmaxf(cnt, 1.0f));
    if (v == 0.0f) {
        int r = repl[iter * KK + k];
        v = X[(size_t)r * DD + d];
    }
    g_centers[k * DD + d] = v;
    g_isums[k * DD + d] = 0ULL;
    if (d == 0) g_icounts[k] = 0;

    float sq = __fmul_rn(v, v);
    #pragma unroll
    for (int o = 16; o > 0; o >>= 1) sq += __shfl_down_sync(0xffffffffu, sq, o);
    __shared__ float sh[2];
    if ((d & 31) == 0) sh[d >> 5] = sq;
    __syncthreads();
    if (d == 0) g_c2[k] = __fadd_rn(sh[0], sh[1]);
}

// ---------------- output: [assignments as float | centers] -----------------
__global__ void out_kernel(float* __restrict__ out) {
    int i = blockIdx.x * blockDim.x + threadIdx.x;
    if (i < NN) {
        out[i] = (float)g_assign[i];
    } else if (i < NN + KK * DD) {
        out[i] = g_centers[i - NN];
    }
}

// ---------------- launch ----------------------------------------------------
extern "C" void kernel_launch(void* const* d_in, const int* in_sizes, int n_in,
                              void* d_out, int out_size)
{
    const float* X    = nullptr;
    const float* C0   = nullptr;
    const int*   repl = nullptr;
    for (int i = 0; i < n_in; i++) {
        if (in_sizes[i] == NN * DD)       X    = (const float*)d_in[i];
        else if (in_sizes[i] == KK * DD)  C0   = (const float*)d_in[i];
        else if (in_sizes[i] == ITERS*KK) repl = (const int*)d_in[i];
    }
    float* out = (float*)d_out;

    cudaFuncSetAttribute(assign_kernel,
                         cudaFuncAttributeMaxDynamicSharedMemorySize, SMEM_REQ);

    prep_kernel<<<KK, DD>>>(C0);
    for (int i = 0; i < ITERS; i++) {
        bconv_kernel<<<32, 256>>>(C0, i);
        assign_kernel<<<NN / MROWS, 256, SMEM_REQ>>>(X, C0, i);
        update_kernel<<<KK, DD>>>(X, repl, i);
    }
    int total = NN + KK * DD;
    out_kernel<<<(total + 255) / 256, 256>>>(out);
}

// round 15
// speedup vs baseline: 1.4370x; 1.0809x over previous
#include <cuda_runtime.h>
#include <cuda_bf16.h>

#define NN 131072
#define DD 64
#define KK 512
#define ITERS 5
#define NCHUNKS 4

// heterogeneous partition: tensor CTAs handle first TROWS rows (128/CTA),
// scalar CTAs handle the rest (256/CTA)
#define NTB 424
#define TROWS (NTB * 128)            // 54272
#define NSB ((NN - TROWS) / 256)     // 300
#define GRID (NTB + NSB)             // 724

#define FP_SCALE 1099511627776.0f          // 2^40
#define FP_INV   (1.0 / 1099511627776.0)   // 2^-40

// ---- smem layout (dynamic; tensor path) ----
#define SM_A     0            // 32KB: A bf16 hi/lo frags
#define SM_B     32768        // 2 x 32KB: B frags
#define SM_C2    98304        // 512 f
#define SM_RB1   100352
#define SM_RB2   101376
#define SM_RI1   102400
#define SM_RI2   103424
#define SM_BIDX  104448
#define SMEM_REQ 104960
// scalar path reuses [0 .. 18KB) of the same region

// ---------------- scratch (device globals; no allocation allowed) ----------
__device__ __align__(256) float g_centers[KK * DD];
__device__ float g_c2[KK];
__device__ __align__(256) unsigned long long g_isums[KK * DD];
__device__ int   g_icounts[KK];
__device__ int   g_assign[NN];
__device__ __align__(256) uint4 g_bcvt[NCHUNKS * 16 * 4 * 32];

// ---------------- helpers ----------------------------------------------------
__device__ __forceinline__ unsigned smem_u32(const void* p) {
    unsigned a;
    asm("{ .reg .u64 t; cvta.to.shared.u64 t, %1; cvt.u32.u64 %0, t; }"
        : "=r"(a) : "l"(p));
    return a;
}
__device__ __forceinline__ unsigned long long fma2(unsigned long long a,
                                                   unsigned long long b,
                                                   unsigned long long c) {
    unsigned long long d;
    asm("fma.rn.f32x2 %0, %1, %2, %3;" : "=l"(d) : "l"(a), "l"(b), "l"(c));
    return d;
}
__device__ __forceinline__ float lo32(unsigned long long v) {
    return __uint_as_float((unsigned)v);
}
__device__ __forceinline__ float hi32(unsigned long long v) {
    return __uint_as_float((unsigned)(v >> 32));
}
__device__ __forceinline__ ulonglong2 lds_v2u64(unsigned a) {
    ulonglong2 v;
    asm("ld.shared.v2.u64 {%0,%1}, [%2];" : "=l"(v.x), "=l"(v.y) : "r"(a));
    return v;
}
__device__ __forceinline__ unsigned pack_hi(float a, float b) {
    unsigned ua = (unsigned)__bfloat16_as_ushort(__float2bfloat16(a));
    unsigned ub = (unsigned)__bfloat16_as_ushort(__float2bfloat16(b));
    return ua | (ub << 16);
}
__device__ __forceinline__ unsigned pack_lo(float a, float b) {
    float ah = __bfloat162float(__float2bfloat16(a));
    float bh = __bfloat162float(__float2bfloat16(b));
    return pack_hi(__fsub_rn(a, ah), __fsub_rn(b, bh));
}
__device__ __forceinline__ void sts128(unsigned a, unsigned x, unsigned y,
                                       unsigned z, unsigned w) {
    asm volatile("st.shared.v4.b32 [%0], {%1,%2,%3,%4};"
                 :: "r"(a), "r"(x), "r"(y), "r"(z), "r"(w) : "memory");
}
__device__ __forceinline__ void stsf32(unsigned a, float v) {
    asm volatile("st.shared.f32 [%0], %1;" :: "r"(a), "f"(v) : "memory");
}
__device__ __forceinline__ void stsi32(unsigned a, int v) {
    asm volatile("st.shared.b32 [%0], %1;" :: "r"(a), "r"(v) : "memory");
}
__device__ __forceinline__ float ldsf32(unsigned a) {
    float v; asm("ld.shared.f32 %0, [%1];" : "=f"(v) : "r"(a)); return v;
}
__device__ __forceinline__ int ldsi32(unsigned a) {
    int v; asm("ld.shared.b32 %0, [%1];" : "=r"(v) : "r"(a)); return v;
}
__device__ __forceinline__ uint4 lds128(unsigned a) {
    uint4 v;
    asm("ld.shared.v4.b32 {%0,%1,%2,%3}, [%4];"
        : "=r"(v.x), "=r"(v.y), "=r"(v.z), "=r"(v.w) : "r"(a));
    return v;
}
__device__ __forceinline__ float2 lds_f2(unsigned a) {
    float2 v;
    asm("ld.shared.v2.f32 {%0,%1}, [%2];" : "=f"(v.x), "=f"(v.y) : "r"(a));
    return v;
}
__device__ __forceinline__ void cp_async16(unsigned s, const void* g) {
    asm volatile("cp.async.cg.shared.global [%0], [%1], 16;\n" :: "r"(s), "l"(g));
}
__device__ __forceinline__ void cp_commit() {
    asm volatile("cp.async.commit_group;\n");
}
__device__ __forceinline__ void cp_wait1() {
    asm volatile("cp.async.wait_group 1;\n");
}
__device__ __forceinline__ void cp_wait0() {
    asm volatile("cp.async.wait_group 0;\n");
}
__device__ __forceinline__ void red_add_u64(unsigned long long* p, unsigned long long v) {
    asm volatile("red.global.add.u64 [%0], %1;\n" :: "l"(p), "l"(v) : "memory");
}
__device__ __forceinline__ void mma_bf16(float* c, uint4 a, unsigned b0, unsigned b1) {
    asm volatile(
        "mma.sync.aligned.m16n8k16.row.col.f32.bf16.bf16.f32 "
        "{%0,%1,%2,%3}, {%4,%5,%6,%7}, {%8,%9}, {%0,%1,%2,%3};"
        : "+f"(c[0]), "+f"(c[1]), "+f"(c[2]), "+f"(c[3])
        : "r"(a.x), "r"(a.y), "r"(a.z), "r"(a.w), "r"(b0), "r"(b1));
}
__device__ __forceinline__ void top2_update(float& b1, int& i1, float& b2, int& i2,
                                            float m, int idx) {
    if (m < b1)      { b2 = b1; i2 = i1; b1 = m; i1 = idx; }
    else if (m < b2) { b2 = m;  i2 = idx; }
}

// ---------------- prep ------------------------------------------------------
__global__ void prep_kernel(const float* __restrict__ centers0) {
    int k = blockIdx.x;
    int d = threadIdx.x;
    float v = centers0[k * DD + d];
    g_isums[k * DD + d] = 0ULL;
    if (d == 0) g_icounts[k] = 0;

    float s = __fmul_rn(v, v);
    #pragma unroll
    for (int o = 16; o > 0; o >>= 1) s += __shfl_down_sync(0xffffffffu, s, o);
    __shared__ float sh[2];
    if ((d & 31) == 0) sh[d >> 5] = s;
    __syncthreads();
    if (d == 0) g_c2[k] = __fadd_rn(sh[0], sh[1]);
}

// ---------------- bconv -----------------------------------------------------
__global__ void bconv_kernel(const float* __restrict__ centers0, int iter) {
    const float* __restrict__ C = (iter == 0) ? centers0 : g_centers;
    int idx = blockIdx.x * blockDim.x + threadIdx.x;   // 0..8191
    int gc = idx >> 4;
    int rem = idx & 15;
    int s = rem >> 2, q = rem & 3;
    int k0 = 16 * s + 2 * q;

    const float* row = C + gc * DD;
    float v00 = row[k0],     v01 = row[k0 + 1];
    float v10 = row[k0 + 8], v11 = row[k0 + 9];
    unsigned hb0 = pack_hi(v00, v01), hb1 = pack_hi(v10, v11);
    unsigned lb0 = pack_lo(v00, v01), lb1 = pack_lo(v10, v11);

    int c  = gc >> 7;
    int np = gc & 127;
    int nt = np >> 3, g = np & 7;
    int l  = g * 4 + q;
    g_bcvt[((c * 16 + nt) * 4 + s) * 32 + l] = make_uint4(hb0, hb1, lb0, lb1);
}

// ---------------- heterogeneous assign kernel ------------------------------
__global__ __launch_bounds__(256, 2) void assign_kernel(
    const float* __restrict__ X,
    const float* __restrict__ centers0,
    int iter)
{
    const float* __restrict__ C = (iter == 0) ? centers0 : g_centers;

    extern __shared__ __align__(16) char smem_raw[];
    const unsigned base = smem_u32(smem_raw);
    const int tid = threadIdx.x;

    if (blockIdx.x < NTB) {
        // =================== TENSOR PATH (rows 0 .. TROWS) ===================
        const unsigned Ab  = base + SM_A;
        const unsigned Bb  = base + SM_B;
        const unsigned C2b = base + SM_C2;

        const int l = tid & 31, w = tid >> 5;
        const int wm = w & 3, wn = w >> 2;
        const int g = l >> 2, q = l & 3;

        const float* Xg = X + (size_t)blockIdx.x * 128 * DD;

        #pragma unroll
        for (int c0 = 0; c0 < 2; c0++) {
            const char* src = (const char*)&g_bcvt[c0 * 2048];
            unsigned dstb = Bb + (unsigned)c0 * 32768u;
            #pragma unroll
            for (int k = 0; k < 8; k++)
                cp_async16(dstb + tid * 16 + k * 4096, src + tid * 16 + k * 4096);
            cp_commit();
        }

        #pragma unroll
        for (int i = 0; i < 2; i++)
            stsf32(C2b + (tid + i * 256) * 4, g_c2[tid + i * 256]);

        {
            const int h = w >> 2, s = w & 3;
            const int k0 = 16 * s + 2 * q;
            #pragma unroll
            for (int mt = 0; mt < 8; mt++) {
                const float* r0p = Xg + (mt * 16 + g) * DD + k0;
                const float* r1p = r0p + 8 * DD;
                unsigned pa0, pa1, pa2, pa3;
                if (h == 0) {
                    pa0 = pack_hi(r0p[0], r0p[1]);
                    pa1 = pack_hi(r1p[0], r1p[1]);
                    pa2 = pack_hi(r0p[8], r0p[9]);
                    pa3 = pack_hi(r1p[8], r1p[9]);
                } else {
                    pa0 = pack_lo(r0p[0], r0p[1]);
                    pa1 = pack_lo(r1p[0], r1p[1]);
                    pa2 = pack_lo(r0p[8], r0p[9]);
                    pa3 = pack_lo(r1p[8], r1p[9]);
                }
                sts128(Ab + (((mt * 2 + h) * 4 + s) * 32 + l) * 16, pa0, pa1, pa2, pa3);
            }
        }
        __syncthreads();

        float b1v[2][2], b2v[2][2];
        int   i1v[2][2], i2v[2][2];
        #pragma unroll
        for (int mi = 0; mi < 2; mi++)
            #pragma unroll
            for (int u = 0; u < 2; u++) {
                b1v[mi][u] = 3.4e38f; b2v[mi][u] = 3.4e38f;
                i1v[mi][u] = 0;       i2v[mi][u] = 0;
            }

        for (int c = 0; c < NCHUNKS; c++) {
            if (c == NCHUNKS - 1) cp_wait0(); else cp_wait1();
            __syncthreads();
            const unsigned bufb = Bb + (unsigned)(c & 1) * 32768u;

            float acc[2][8][4];
            #pragma unroll
            for (int mi = 0; mi < 2; mi++)
                #pragma unroll
                for (int nt = 0; nt < 8; nt++)
                    #pragma unroll
                    for (int j = 0; j < 4; j++) acc[mi][nt][j] = 0.0f;

            #pragma unroll
            for (int s = 0; s < 4; s++) {
                uint4 ahi[2], alo[2];
                #pragma unroll
                for (int mi = 0; mi < 2; mi++) {
                    ahi[mi] = lds128(Ab + ((((2 * wm + mi) * 2 + 0) * 4 + s) * 32 + l) * 16);
                    alo[mi] = lds128(Ab + ((((2 * wm + mi) * 2 + 1) * 4 + s) * 32 + l) * 16);
                }
                uint4 bf[8];
                #pragma unroll
                for (int nt = 0; nt < 8; nt++)
                    bf[nt] = lds128(bufb + (((8 * wn + nt) * 4 + s) * 32 + l) * 16);
                #pragma unroll
                for (int nt = 0; nt < 8; nt++)
                    #pragma unroll
                    for (int mi = 0; mi < 2; mi++)
                        mma_bf16(acc[mi][nt], ahi[mi], bf[nt].x, bf[nt].y);
                #pragma unroll
                for (int nt = 0; nt < 8; nt++)
                    #pragma unroll
                    for (int mi = 0; mi < 2; mi++)
                        mma_bf16(acc[mi][nt], ahi[mi], bf[nt].z, bf[nt].w);
                #pragma unroll
                for (int nt = 0; nt < 8; nt++)
                    #pragma unroll
                    for (int mi = 0; mi < 2; mi++)
                        mma_bf16(acc[mi][nt], alo[mi], bf[nt].x, bf[nt].y);
            }

            #pragma unroll
            for (int nt = 0; nt < 8; nt++) {
                const int colb = c * 128 + (8 * wn + nt) * 8 + 2 * q;
                float2 cc = lds_f2(C2b + colb * 4);
                #pragma unroll
                for (int mi = 0; mi < 2; mi++)
                    #pragma unroll
                    for (int u = 0; u < 2; u++) {
                        float m0 = __fsub_rn(cc.x, __fmul_rn(2.0f, acc[mi][nt][u * 2 + 0]));
                        float m1 = __fsub_rn(cc.y, __fmul_rn(2.0f, acc[mi][nt][u * 2 + 1]));
                        top2_update(b1v[mi][u], i1v[mi][u], b2v[mi][u], i2v[mi][u], m0, colb);
                        top2_update(b1v[mi][u], i1v[mi][u], b2v[mi][u], i2v[mi][u], m1, colb + 1);
                    }
            }
            __syncthreads();

            if (c + 2 < NCHUNKS) {
                const char* src = (const char*)&g_bcvt[(c + 2) * 2048];
                unsigned dstb = Bb + (unsigned)(c & 1) * 32768u;
                #pragma unroll
                for (int k = 0; k < 8; k++)
                    cp_async16(dstb + tid * 16 + k * 4096, src + tid * 16 + k * 4096);
                cp_commit();
            }
        }

        #pragma unroll
        for (int mi = 0; mi < 2; mi++)
            #pragma unroll
            for (int u = 0; u < 2; u++) {
                float B1 = b1v[mi][u], B2 = b2v[mi][u];
                int   I1 = i1v[mi][u], I2 = i2v[mi][u];
                #pragma unroll
                for (int off = 1; off <= 2; off <<= 1) {
                    float oB1 = __shfl_xor_sync(0xffffffffu, B1, off);
                    int   oI1 = __shfl_xor_sync(0xffffffffu, I1, off);
                    float oB2 = __shfl_xor_sync(0xffffffffu, B2, off);
                    int   oI2 = __shfl_xor_sync(0xffffffffu, I2, off);
                    if (oB1 < B1 || (oB1 == B1 && oI1 < I1)) {
                        if (B1 < oB2 || (B1 == oB2 && I1 < oI2)) { B2 = B1; I2 = I1; }
                        else { B2 = oB2; I2 = oI2; }
                        B1 = oB1; I1 = oI1;
                    } else {
                        if (oB1 < B2) { B2 = oB1; I2 = oI1; }
                    }
                }
                if (q == 0) {
                    int row = (2 * wm + mi) * 16 + u * 8 + g;
                    stsf32(base + SM_RB1 + (wn * 128 + row) * 4, B1);
                    stsf32(base + SM_RB2 + (wn * 128 + row) * 4, B2);
                    stsi32(base + SM_RI1 + (wn * 128 + row) * 4, I1);
                    stsi32(base + SM_RI2 + (wn * 128 + row) * 4, I2);
                }
            }
        __syncthreads();

        if (tid < 128) {
            int row = tid;
            float B1 = ldsf32(base + SM_RB1 + row * 4);
            float B2 = ldsf32(base + SM_RB2 + row * 4);
            int   I1 = ldsi32(base + SM_RI1 + row * 4);
            float oB1 = ldsf32(base + SM_RB1 + (128 + row) * 4);
            float oB2 = ldsf32(base + SM_RB2 + (128 + row) * 4);
            int   oI1 = ldsi32(base + SM_RI1 + (128 + row) * 4);
            if (oB1 < B1) {
                if (B1 < oB2) B2 = B1;
                else          B2 = oB2;
                B1 = oB1; I1 = oI1;
            } else {
                if (oB1 < B2) B2 = oB1;
            }

            int bi = I1;
            if (B2 - B1 < 1.5e-3f) {
                const float* xr = Xg + row * DD;
                float x2 = 0.0f;
                #pragma unroll
                for (int d = 0; d < DD; d++) x2 = __fmaf_rn(xr[d], xr[d], x2);
                float bb = 3.4e38f;
                int   ib = 0;
                for (int kc = 0; kc < KK; kc++) {
                    const float* cr = C + (size_t)kc * DD;
                    float d0 = 0.0f, d1 = 0.0f, d2a = 0.0f, d3 = 0.0f;
                    #pragma unroll
                    for (int d = 0; d < DD; d += 4) {
                        d0 = __fmaf_rn(xr[d],     cr[d],     d0);
                        d1 = __fmaf_rn(xr[d + 1], cr[d + 1], d1);
                        d2a= __fmaf_rn(xr[d + 2], cr[d + 2], d2a);
                        d3 = __fmaf_rn(xr[d + 3], cr[d + 3], d3);
                    }
                    float dot = __fadd_rn(__fadd_rn(d0, d1), __fadd_rn(d2a, d3));
                    float cc  = ldsf32(C2b + kc * 4);
                    float dd  = __fsub_rn(__fadd_rn(x2, cc), __fmul_rn(2.0f, dot));
                    if (dd < bb) { bb = dd; ib = kc; }
                }
                bi = ib;
            }
            stsi32(base + SM_BIDX + row * 4, bi);
            g_assign[blockIdx.x * 128 + row] = bi;
            atomicAdd(&g_icounts[bi], 1);
        }
        __syncthreads();

        {
            int row = tid >> 1, half = tid & 1;
            int bi = ldsi32(base + SM_BIDX + row * 4);
            const float4* xr = (const float4*)(Xg + row * DD + half * 32);
            unsigned long long* s = &g_isums[(size_t)bi * DD + half * 32];
            #pragma unroll
            for (int qq = 0; qq < 8; qq++) {
                float4 v = xr[qq];
                red_add_u64(&s[qq * 4 + 0], (unsigned long long)llrintf(v.x * FP_SCALE));
                red_add_u64(&s[qq * 4 + 1], (unsigned long long)llrintf(v.y * FP_SCALE));
                red_add_u64(&s[qq * 4 + 2], (unsigned long long)llrintf(v.z * FP_SCALE));
                red_add_u64(&s[qq * 4 + 3], (unsigned long long)llrintf(v.w * FP_SCALE));
            }
        }
    } else {
        // =================== SCALAR PATH (rows TROWS .. NN) ==================
        // 256 threads, 1 row/thread, NT=32 center tiles double-buffered.
        // Exact fp32, accumulation order identical to validated round-3 kernel.
        const unsigned sb0 = base, sb1 = base + 8192;
        const unsigned c2b = base + 16384;

        const int blk = blockIdx.x - NTB;
        const int row = TROWS + blk * 256 + tid;

        #pragma unroll
        for (int i = 0; i < 2; i++)
            stsf32(c2b + (tid + i * 256) * 4, g_c2[tid + i * 256]);

        // prologue: tiles 0,1 (8KB each = 512 chunks, 2/thread)
        #pragma unroll
        for (int t0 = 0; t0 < 2; t0++) {
            const char* src = (const char*)(C + (size_t)t0 * 32 * DD);
            unsigned dst = t0 ? sb1 : sb0;
            #pragma unroll
            for (int k = 0; k < 2; k++)
                cp_async16(dst + tid * 16 + k * 4096, src + tid * 16 + k * 4096);
            cp_commit();
        }

        // X row -> registers (packed f32x2)
        unsigned long long x0[32];
        {
            const ulonglong2* R0 = (const ulonglong2*)(X + (size_t)row * DD);
            #pragma unroll
            for (int qq = 0; qq < 16; qq++) {
                ulonglong2 a = R0[qq];
                x0[2 * qq] = a.x; x0[2 * qq + 1] = a.y;
            }
        }
        float x2_0;
        {
            unsigned long long a0 = 0ULL, b0 = 0ULL;
            #pragma unroll
            for (int p = 0; p < 32; p += 2) {
                a0 = fma2(x0[p],     x0[p],     a0);
                b0 = fma2(x0[p + 1], x0[p + 1], b0);
            }
            x2_0 = __fadd_rn(__fadd_rn(lo32(a0), hi32(a0)),
                             __fadd_rn(lo32(b0), hi32(b0)));
        }

        float best0 = 3.4e38f;
        int   bi0 = 0;

        for (int t = 0; t < 16; t++) {
            if (t == 15) cp_wait0(); else cp_wait1();
            __syncthreads();
            const unsigned buf = (t & 1) ? sb1 : sb0;

            #pragma unroll 1
            for (int j = 0; j < 32; j += 2) {
                const unsigned ca = buf + j * 256;
                const unsigned cb = ca + 256;
                unsigned long long A0 = 0ULL, B0 = 0ULL, A1 = 0ULL, B1 = 0ULL;
                #pragma unroll
                for (int qq = 0; qq < 16; qq++) {
                    ulonglong2 u = lds_v2u64(ca + qq * 16);
                    ulonglong2 v = lds_v2u64(cb + qq * 16);
                    A0 = fma2(x0[2 * qq],     u.x, A0);
                    A1 = fma2(x0[2 * qq],     v.x, A1);
                    B0 = fma2(x0[2 * qq + 1], u.y, B0);
                    B1 = fma2(x0[2 * qq + 1], v.y, B1);
                }
                float dot0 = __fadd_rn(__fadd_rn(lo32(A0), hi32(A0)),
                                       __fadd_rn(lo32(B0), hi32(B0)));
                float dot1 = __fadd_rn(__fadd_rn(lo32(A1), hi32(A1)),
                                       __fadd_rn(lo32(B1), hi32(B1)));
                float cc0 = ldsf32(c2b + (t * 32 + j) * 4);
                float cc1 = ldsf32(c2b + (t * 32 + j + 1) * 4);
                float d20 = __fsub_rn(__fadd_rn(x2_0, cc0), __fmul_rn(2.0f, dot0));
                float d21 = __fsub_rn(__fadd_rn(x2_0, cc1), __fmul_rn(2.0f, dot1));
                int kg = t * 32 + j;
                if (d20 < best0) { best0 = d20; bi0 = kg; }
                if (d21 < best0) { best0 = d21; bi0 = kg + 1; }
            }
            __syncthreads();

            if (t + 2 < 16) {
                const char* src = (const char*)(C + (size_t)(t + 2) * 32 * DD);
                unsigned dst = (t & 1) ? sb1 : sb0;
                #pragma unroll
                for (int k = 0; k < 2; k++)
                    cp_async16(dst + tid * 16 + k * 4096, src + tid * 16 + k * 4096);
                cp_commit();
            }
        }

        g_assign[row] = bi0;
        atomicAdd(&g_icounts[bi0], 1);
        unsigned long long* s = &g_isums[(size_t)bi0 * DD];
        #pragma unroll
        for (int p = 0; p < 32; p++) {
            red_add_u64(&s[2 * p],     (unsigned long long)llrintf(lo32(x0[p]) * FP_SCALE));
            red_add_u64(&s[2 * p + 1], (unsigned long long)llrintf(hi32(x0[p]) * FP_SCALE));
        }
    }
}

// ---------------- centers update -------------------------------------------
__global__ void update_kernel(const float* __restrict__ X,
                              const int* __restrict__ repl,
                              int iter)
{
    int k = blockIdx.x;
    int d = threadIdx.x;
    int icnt = g_icounts[k];
    long long ll = (long long)g_isums[k * DD + d];
    float s   = (float)((double)ll * FP_INV);
    float cnt = (float)icnt;
    float v   = __fdiv_rn(s, fmaxf(cnt, 1.0f));
    if (v == 0.0f) {
        int r = repl[iter * KK + k];
        v = X[(size_t)r * DD + d];
    }
    g_centers[k * DD + d] = v;
    g_isums[k * DD + d] = 0ULL;
    if (d == 0) g_icounts[k] = 0;

    float sq = __fmul_rn(v, v);
    #pragma unroll
    for (int o = 16; o > 0; o >>= 1) sq += __shfl_down_sync(0xffffffffu, sq, o);
    __shared__ float sh[2];
    if ((d & 31) == 0) sh[d >> 5] = sq;
    __syncthreads();
    if (d == 0) g_c2[k] = __fadd_rn(sh[0], sh[1]);
}

// ---------------- output ----------------------------------------------------
__global__ void out_kernel(float* __restrict__ out) {
    int i = blockIdx.x * blockDim.x + threadIdx.x;
    if (i < NN) {
        out[i] = (float)g_assign[i];
    } else if (i < NN + KK * DD) {
        out[i] = g_centers[i - NN];
    }
}

// ---------------- launch ----------------------------------------------------
extern "C" void kernel_launch(void* const* d_in, const int* in_sizes, int n_in,
                              void* d_out, int out_size)
{
    const float* X    = nullptr;
    const float* C0   = nullptr;
    const int*   repl = nullptr;
    for (int i = 0; i < n_in; i++) {
        if (in_sizes[i] == NN * DD)       X    = (const float*)d_in[i];
        else if (in_sizes[i] == KK * DD)  C0   = (const float*)d_in[i];
        else if (in_sizes[i] == ITERS*KK) repl = (const int*)d_in[i];
    }
    float* out = (float*)d_out;

    cudaFuncSetAttribute(assign_kernel,
                         cudaFuncAttributeMaxDynamicSharedMemorySize, SMEM_REQ);

    prep_kernel<<<KK, DD>>>(C0);
    for (int i = 0; i < ITERS; i++) {
        bconv_kernel<<<32, 256>>>(C0, i);
        assign_kernel<<<GRID, 256, SMEM_REQ>>>(X, C0, i);
        update_kernel<<<KK, DD>>>(X, repl, i);
    }
    int total = NN + KK * DD;
    out_kernel<<<(total + 255) / 256, 256>>>(out);
}

// round 16
// speedup vs baseline: 1.6341x; 1.1372x over previous
#include <cuda_runtime.h>

#define NN 131072
#define DD 64
#define KK 512
#define ITERS 5
#define NT 32            // centers per smem tile
#define NTILES (KK / NT)

#define FP_SCALE 1099511627776.0f          // 2^40 (exact exponent shift)
#define FP_INV   (1.0 / 1099511627776.0)   // 2^-40 (double)

// ---------------- scratch (device globals; no allocation allowed) ----------
__device__ __align__(256) float g_centers[KK * DD];
__device__ float g_c2[KK];
__device__ __align__(256) unsigned long long g_isums[KK * DD];
__device__ int   g_icounts[KK];
__device__ int   g_assign[NN];

// ---------------- packed f32x2 helpers -------------------------------------
__device__ __forceinline__ unsigned long long fma2(unsigned long long a,
                                                   unsigned long long b,
                                                   unsigned long long c) {
    unsigned long long d;
    asm("fma.rn.f32x2 %0, %1, %2, %3;" : "=l"(d) : "l"(a), "l"(b), "l"(c));
    return d;
}
__device__ __forceinline__ float lo32(unsigned long long v) {
    return __uint_as_float((unsigned)v);
}
__device__ __forceinline__ float hi32(unsigned long long v) {
    return __uint_as_float((unsigned)(v >> 32));
}

// ---------------- cp.async + reduction helpers ------------------------------
__device__ __forceinline__ void cp_async16(unsigned s, const void* g) {
    asm volatile("cp.async.cg.shared.global [%0], [%1], 16;\n" :: "r"(s), "l"(g));
}
__device__ __forceinline__ void cp_commit() {
    asm volatile("cp.async.commit_group;\n");
}
__device__ __forceinline__ void cp_wait1() {
    asm volatile("cp.async.wait_group 1;\n");
}
__device__ __forceinline__ void cp_wait0() {
    asm volatile("cp.async.wait_group 0;\n");
}
__device__ __forceinline__ void red_add_u64(unsigned long long* p, unsigned long long v) {
    asm volatile("red.global.add.u64 [%0], %1;\n" :: "l"(p), "l"(v) : "memory");
}

// ---------------- prep: zero sums/counts, c2 of initial centers ------------
__global__ void prep_kernel(const float* __restrict__ centers0) {
    int k = blockIdx.x;
    int d = threadIdx.x;
    float v = centers0[k * DD + d];
    g_isums[k * DD + d] = 0ULL;
    if (d == 0) g_icounts[k] = 0;

    float s = __fmul_rn(v, v);
    #pragma unroll
    for (int o = 16; o > 0; o >>= 1) s += __shfl_down_sync(0xffffffffu, s, o);
    __shared__ float sh[2];
    if ((d & 31) == 0) sh[d >> 5] = s;
    __syncthreads();
    if (d == 0) g_c2[k] = __fadd_rn(sh[0], sh[1]);
}

// ---------------- assign + accumulate (fused, warp-rotated scan) ------------
// 128 threads/block, each thread owns 2 rows of X (full D=64 in registers as
// 32 packed f32x2 each). Centers staged 32 at a time via cp.async double
// buffering. Each warp scans the tile's centers in a rotated order
// (warp w starts at center w*8) to decorrelate warp phases and keep the fma
// pipe fed. d2 arithmetic per (row,center) is bit-identical to the validated
// round-2 kernel; argmin uses an explicit lowest-index tie-break, making the
// result independent of scan order (exact argmin semantics).
__global__ __launch_bounds__(128, 3) void assign_kernel(
    const float* __restrict__ X,
    const float* __restrict__ centers0,
    int iter)
{
    const float* __restrict__ C = (iter == 0) ? centers0 : g_centers;

    __shared__ __align__(16) float sbuf[2][NT * DD];   // 2 x 8KB
    __shared__ float sc2[KK];

    const int tid  = threadIdx.x;
    const int wrot = (tid >> 5) * 8;                   // per-warp rotation
    const int row0 = blockIdx.x * 256 + tid;
    const int row1 = row0 + 128;

    // stage all c2 once (consumed only after the first barrier)
    #pragma unroll
    for (int i = 0; i < KK / 128; i++) sc2[tid + i * 128] = g_c2[tid + i * 128];

    unsigned sb[2];
    sb[0] = (unsigned)__cvta_generic_to_shared(&sbuf[0][0]);
    sb[1] = (unsigned)__cvta_generic_to_shared(&sbuf[1][0]);

    // prologue: stage tiles 0 and 1
    {
        const char* src0 = (const char*)(C);
        const char* src1 = (const char*)(C + (size_t)NT * DD);
        #pragma unroll
        for (int k = 0; k < 4; k++)
            cp_async16(sb[0] + tid * 16 + k * 2048, src0 + tid * 16 + k * 2048);
        cp_commit();
        #pragma unroll
        for (int k = 0; k < 4; k++)
            cp_async16(sb[1] + tid * 16 + k * 2048, src1 + tid * 16 + k * 2048);
        cp_commit();
    }

    // x rows resident in registers (packed f32x2)
    unsigned long long x0[32], x1[32];
    {
        const ulonglong2* R0 = (const ulonglong2*)(X + (size_t)row0 * DD);
        const ulonglong2* R1 = (const ulonglong2*)(X + (size_t)row1 * DD);
        #pragma unroll
        for (int q = 0; q < 16; q++) {
            ulonglong2 a = R0[q];
            ulonglong2 b = R1[q];
            x0[2 * q] = a.x; x0[2 * q + 1] = a.y;
            x1[2 * q] = b.x; x1[2 * q + 1] = b.y;
        }
    }
    // x^2 per row (packed) — identical order to round 1/2
    float x2_0, x2_1;
    {
        unsigned long long a0 = 0ULL, b0 = 0ULL, a1 = 0ULL, b1 = 0ULL;
        #pragma unroll
        for (int p = 0; p < 32; p += 2) {
            a0 = fma2(x0[p],     x0[p],     a0);
            b0 = fma2(x0[p + 1], x0[p + 1], b0);
            a1 = fma2(x1[p],     x1[p],     a1);
            b1 = fma2(x1[p + 1], x1[p + 1], b1);
        }
        x2_0 = __fadd_rn(__fadd_rn(lo32(a0), hi32(a0)),
                         __fadd_rn(lo32(b0), hi32(b0)));
        x2_1 = __fadd_rn(__fadd_rn(lo32(a1), hi32(a1)),
                         __fadd_rn(lo32(b1), hi32(b1)));
    }

    float best0 = 3.4e38f, best1 = 3.4e38f;
    int   bi0 = 0, bi1 = 0;

    for (int t = 0; t < NTILES; t++) {
        if (t == NTILES - 1) cp_wait0(); else cp_wait1();
        __syncthreads();
        const int buf = t & 1;

        #pragma unroll 1
        for (int j0 = 0; j0 < NT; j0++) {
            const int j = (j0 + wrot) & (NT - 1);      // warp-rotated scan
            const ulonglong2* c = (const ulonglong2*)&sbuf[buf][j * DD];
            unsigned long long A0 = 0ULL, B0 = 0ULL, A1 = 0ULL, B1 = 0ULL;
            #pragma unroll
            for (int q = 0; q < 16; q++) {
                ulonglong2 cc2 = c[q];                 // c[2q], c[2q+1]
                A0 = fma2(x0[2 * q],     cc2.x, A0);
                A1 = fma2(x1[2 * q],     cc2.x, A1);
                B0 = fma2(x0[2 * q + 1], cc2.y, B0);
                B1 = fma2(x1[2 * q + 1], cc2.y, B1);
            }
            float dot0 = __fadd_rn(__fadd_rn(lo32(A0), hi32(A0)),
                                   __fadd_rn(lo32(B0), hi32(B0)));
            float dot1 = __fadd_rn(__fadd_rn(lo32(A1), hi32(A1)),
                                   __fadd_rn(lo32(B1), hi32(B1)));
            float cc = sc2[t * NT + j];
            float d20 = __fsub_rn(__fadd_rn(x2_0, cc), __fmul_rn(2.0f, dot0));
            float d21 = __fsub_rn(__fadd_rn(x2_1, cc), __fmul_rn(2.0f, dot1));
            int kg = t * NT + j;
            // exact argmin semantics: lowest index wins ties
            if (d20 < best0 || (d20 == best0 && kg < bi0)) { best0 = d20; bi0 = kg; }
            if (d21 < best1 || (d21 == best1 && kg < bi1)) { best1 = d21; bi1 = kg; }
        }
        __syncthreads();

        if (t + 2 < NTILES) {
            const char* src = (const char*)(C + (size_t)(t + 2) * NT * DD);
            #pragma unroll
            for (int k = 0; k < 4; k++)
                cp_async16(sb[buf] + tid * 16 + k * 2048, src + tid * 16 + k * 2048);
            cp_commit();
        }
    }

    // ---- epilogue: deterministic int64 fixed-point reductions ----
    g_assign[row0] = bi0;
    g_assign[row1] = bi1;
    atomicAdd(&g_icounts[bi0], 1);
    atomicAdd(&g_icounts[bi1], 1);
    unsigned long long* s0 = &g_isums[(size_t)bi0 * DD];
    unsigned long long* s1 = &g_isums[(size_t)bi1 * DD];
    #pragma unroll
    for (int p = 0; p < 32; p++) {
        red_add_u64(&s0[2 * p],     (unsigned long long)llrintf(lo32(x0[p]) * FP_SCALE));
        red_add_u64(&s0[2 * p + 1], (unsigned long long)llrintf(hi32(x0[p]) * FP_SCALE));
        red_add_u64(&s1[2 * p],     (unsigned long long)llrintf(lo32(x1[p]) * FP_SCALE));
        red_add_u64(&s1[2 * p + 1], (unsigned long long)llrintf(hi32(x1[p]) * FP_SCALE));
    }
}

// ---------------- centers update (+ c2, + reset sums/counts) ---------------
__global__ void update_kernel(const float* __restrict__ X,
                              const int* __restrict__ repl,
                              int iter)
{
    int k = blockIdx.x;
    int d = threadIdx.x;
    int icnt = g_icounts[k];
    long long ll = (long long)g_isums[k * DD + d];
    float s   = (float)((double)ll * FP_INV);
    float cnt = (float)icnt;
    float v   = __fdiv_rn(s, fmaxf(cnt, 1.0f));
    if (v == 0.0f) {
        int r = repl[iter * KK + k];
        v = X[(size_t)r * DD + d];
    }
    g_centers[k * DD + d] = v;
    g_isums[k * DD + d] = 0ULL;
    if (d == 0) g_icounts[k] = 0;

    float sq = __fmul_rn(v, v);
    #pragma unroll
    for (int o = 16; o > 0; o >>= 1) sq += __shfl_down_sync(0xffffffffu, sq, o);
    __shared__ float sh[2];
    if ((d & 31) == 0) sh[d >> 5] = sq;
    __syncthreads();
    if (d == 0) g_c2[k] = __fadd_rn(sh[0], sh[1]);
}

// ---------------- output: [assignments as float | centers] -----------------
__global__ void out_kernel(float* __restrict__ out) {
    int i = blockIdx.x * blockDim.x + threadIdx.x;
    if (i < NN) {
        out[i] = (float)g_assign[i];
    } else if (i < NN + KK * DD) {
        out[i] = g_centers[i - NN];
    }
}

// ---------------- launch ----------------------------------------------------
extern "C" void kernel_launch(void* const* d_in, const int* in_sizes, int n_in,
                              void* d_out, int out_size)
{
    const float* X    = nullptr;
    const float* C0   = nullptr;
    const int*   repl = nullptr;
    for (int i = 0; i < n_in; i++) {
        if (in_sizes[i] == NN * DD)       X    = (const float*)d_in[i];
        else if (in_sizes[i] == KK * DD)  C0   = (const float*)d_in[i];
        else if (in_sizes[i] == ITERS*KK) repl = (const int*)d_in[i];
    }
    float* out = (float*)d_out;

    prep_kernel<<<KK, DD>>>(C0);
    for (int i = 0; i < ITERS; i++) {
        assign_kernel<<<NN / 256, 128>>>(X, C0, i);
        update_kernel<<<KK, DD>>>(X, repl, i);
    }
    int total = NN + KK * DD;
    out_kernel<<<(total + 255) / 256, 256>>>(out);
}

// round 17
// speedup vs baseline: 1.7459x; 1.0684x over previous
#include <cuda_runtime.h>

#define NN 131072
#define DD 64
#define KK 512
#define ITERS 5
#define NT 32            // centers per smem tile
#define NTILES (KK / NT)
#define RPB 512          // rows per block (256 threads x MR=2)

#define FP_SCALE 1099511627776.0f          // 2^40 (exact exponent shift)
#define FP_INV   (1.0 / 1099511627776.0)   // 2^-40 (double)

// ---------------- scratch (device globals; no allocation allowed) ----------
__device__ __align__(256) float g_centers[KK * DD];
__device__ float g_c2[KK];
__device__ __align__(256) unsigned long long g_isums[KK * DD];
__device__ int   g_icounts[KK];
__device__ int   g_assign[NN];

// ---------------- packed f32x2 helpers -------------------------------------
__device__ __forceinline__ unsigned long long fma2(unsigned long long a,
                                                   unsigned long long b,
                                                   unsigned long long c) {
    unsigned long long d;
    asm("fma.rn.f32x2 %0, %1, %2, %3;" : "=l"(d) : "l"(a), "l"(b), "l"(c));
    return d;
}
__device__ __forceinline__ float lo32(unsigned long long v) {
    return __uint_as_float((unsigned)v);
}
__device__ __forceinline__ float hi32(unsigned long long v) {
    return __uint_as_float((unsigned)(v >> 32));
}
// broadcast 16B shared load: both packed f32x2 operands of one d-chunk
__device__ __forceinline__ ulonglong2 lds_v2u64(unsigned a) {
    ulonglong2 v;
    asm("ld.shared.v2.u64 {%0,%1}, [%2];" : "=l"(v.x), "=l"(v.y) : "r"(a));
    return v;
}

// ---------------- cp.async + reduction helpers ------------------------------
__device__ __forceinline__ void cp_async16(unsigned s, const void* g) {
    asm volatile("cp.async.cg.shared.global [%0], [%1], 16;\n" :: "r"(s), "l"(g));
}
__device__ __forceinline__ void cp_commit() {
    asm volatile("cp.async.commit_group;\n");
}
__device__ __forceinline__ void cp_wait1() {
    asm volatile("cp.async.wait_group 1;\n");
}
__device__ __forceinline__ void cp_wait0() {
    asm volatile("cp.async.wait_group 0;\n");
}
__device__ __forceinline__ void red_add_u64(unsigned long long* p, unsigned long long v) {
    asm volatile("red.global.add.u64 [%0], %1;\n" :: "l"(p), "l"(v) : "memory");
}

// ---------------- prep: zero sums/counts, c2 of initial centers ------------
__global__ void prep_kernel(const float* __restrict__ centers0) {
    int k = blockIdx.x;
    int d = threadIdx.x;
    float v = centers0[k * DD + d];
    g_isums[k * DD + d] = 0ULL;
    if (d == 0) g_icounts[k] = 0;

    float s = __fmul_rn(v, v);
    #pragma unroll
    for (int o = 16; o > 0; o >>= 1) s += __shfl_down_sync(0xffffffffu, s, o);
    __shared__ float sh[2];
    if ((d & 31) == 0) sh[d >> 5] = s;
    __syncthreads();
    if (d == 0) g_c2[k] = __fadd_rn(sh[0], sh[1]);
}

// ---------------- assign + accumulate (fused) ------------------------------
// 256 threads/block, each thread owns 2 rows of X (full D=64 in registers as
// 32 packed f32x2 each) -> 512 rows/block, grid 256 (1 block/SM, ~86% wave
// efficiency; center cp.async traffic amortized over 2x the rows of round 2).
// Centers staged 32 at a time via cp.async double buffering; broadcast
// LDS.128 center reads. Per-(row,center) arithmetic order bit-identical to
// the validated round-2 kernel; ascending scan + strict < = exact argmin.
// Cluster sums in 2^40 fixed-point int64 -> order-independent, deterministic.
__global__ __launch_bounds__(256) void assign_kernel(
    const float* __restrict__ X,
    const float* __restrict__ centers0,
    int iter)
{
    const float* __restrict__ C = (iter == 0) ? centers0 : g_centers;

    __shared__ __align__(16) float sbuf[2][NT * DD];   // 2 x 8KB
    __shared__ float sc2[KK];

    const int tid  = threadIdx.x;
    const int row0 = blockIdx.x * RPB + tid;
    const int row1 = row0 + 256;

    // stage all c2 once (consumed only after the first barrier)
    #pragma unroll
    for (int i = 0; i < KK / 256; i++) sc2[tid + i * 256] = g_c2[tid + i * 256];

    unsigned sb[2];
    sb[0] = (unsigned)__cvta_generic_to_shared(&sbuf[0][0]);
    sb[1] = (unsigned)__cvta_generic_to_shared(&sbuf[1][0]);

    // prologue: stage tiles 0 and 1 (8KB each = 512 chunks, 2/thread)
    {
        const char* src0 = (const char*)(C);
        const char* src1 = (const char*)(C + (size_t)NT * DD);
        #pragma unroll
        for (int k = 0; k < 2; k++)
            cp_async16(sb[0] + tid * 16 + k * 4096, src0 + tid * 16 + k * 4096);
        cp_commit();
        #pragma unroll
        for (int k = 0; k < 2; k++)
            cp_async16(sb[1] + tid * 16 + k * 4096, src1 + tid * 16 + k * 4096);
        cp_commit();
    }

    // x rows resident in registers (packed f32x2)
    unsigned long long x0[32], x1[32];
    {
        const ulonglong2* R0 = (const ulonglong2*)(X + (size_t)row0 * DD);
        const ulonglong2* R1 = (const ulonglong2*)(X + (size_t)row1 * DD);
        #pragma unroll
        for (int q = 0; q < 16; q++) {
            ulonglong2 a = R0[q];
            ulonglong2 b = R1[q];
            x0[2 * q] = a.x; x0[2 * q + 1] = a.y;
            x1[2 * q] = b.x; x1[2 * q + 1] = b.y;
        }
    }
    // x^2 per row (packed) — identical order to rounds 1/2
    float x2_0, x2_1;
    {
        unsigned long long a0 = 0ULL, b0 = 0ULL, a1 = 0ULL, b1 = 0ULL;
        #pragma unroll
        for (int p = 0; p < 32; p += 2) {
            a0 = fma2(x0[p],     x0[p],     a0);
            b0 = fma2(x0[p + 1], x0[p + 1], b0);
            a1 = fma2(x1[p],     x1[p],     a1);
            b1 = fma2(x1[p + 1], x1[p + 1], b1);
        }
        x2_0 = __fadd_rn(__fadd_rn(lo32(a0), hi32(a0)),
                         __fadd_rn(lo32(b0), hi32(b0)));
        x2_1 = __fadd_rn(__fadd_rn(lo32(a1), hi32(a1)),
                         __fadd_rn(lo32(b1), hi32(b1)));
    }

    float best0 = 3.4e38f, best1 = 3.4e38f;
    int   bi0 = 0, bi1 = 0;

    for (int t = 0; t < NTILES; t++) {
        if (t == NTILES - 1) cp_wait0(); else cp_wait1();
        __syncthreads();
        const int buf = t & 1;
        const unsigned bb = sb[buf];

        #pragma unroll 1
        for (int j = 0; j < NT; j++) {
            const unsigned cj = bb + j * 256;
            unsigned long long A0 = 0ULL, B0 = 0ULL, A1 = 0ULL, B1 = 0ULL;
            #pragma unroll
            for (int q = 0; q < 16; q++) {
                ulonglong2 cc2 = lds_v2u64(cj + q * 16);   // c[2q], c[2q+1]
                A0 = fma2(x0[2 * q],     cc2.x, A0);
                A1 = fma2(x1[2 * q],     cc2.x, A1);
                B0 = fma2(x0[2 * q + 1], cc2.y, B0);
                B1 = fma2(x1[2 * q + 1], cc2.y, B1);
            }
            float dot0 = __fadd_rn(__fadd_rn(lo32(A0), hi32(A0)),
                                   __fadd_rn(lo32(B0), hi32(B0)));
            float dot1 = __fadd_rn(__fadd_rn(lo32(A1), hi32(A1)),
                                   __fadd_rn(lo32(B1), hi32(B1)));
            float cc = sc2[t * NT + j];
            float d20 = __fsub_rn(__fadd_rn(x2_0, cc), __fmul_rn(2.0f, dot0));
            float d21 = __fsub_rn(__fadd_rn(x2_1, cc), __fmul_rn(2.0f, dot1));
            int kg = t * NT + j;
            if (d20 < best0) { best0 = d20; bi0 = kg; }
            if (d21 < best1) { best1 = d21; bi1 = kg; }
        }
        __syncthreads();

        if (t + 2 < NTILES) {
            const char* src = (const char*)(C + (size_t)(t + 2) * NT * DD);
            #pragma unroll
            for (int k = 0; k < 2; k++)
                cp_async16(sb[buf] + tid * 16 + k * 4096, src + tid * 16 + k * 4096);
            cp_commit();
        }
    }

    // ---- epilogue: deterministic int64 fixed-point reductions ----
    g_assign[row0] = bi0;
    g_assign[row1] = bi1;
    atomicAdd(&g_icounts[bi0], 1);
    atomicAdd(&g_icounts[bi1], 1);
    unsigned long long* s0 = &g_isums[(size_t)bi0 * DD];
    unsigned long long* s1 = &g_isums[(size_t)bi1 * DD];
    #pragma unroll
    for (int p = 0; p < 32; p++) {
        red_add_u64(&s0[2 * p],     (unsigned long long)llrintf(lo32(x0[p]) * FP_SCALE));
        red_add_u64(&s0[2 * p + 1], (unsigned long long)llrintf(hi32(x0[p]) * FP_SCALE));
        red_add_u64(&s1[2 * p],     (unsigned long long)llrintf(lo32(x1[p]) * FP_SCALE));
        red_add_u64(&s1[2 * p + 1], (unsigned long long)llrintf(hi32(x1[p]) * FP_SCALE));
    }
}

// ---------------- centers update (+ c2, + reset sums/counts) ---------------
__global__ void update_kernel(const float* __restrict__ X,
                              const int* __restrict__ repl,
                              int iter)
{
    int k = blockIdx.x;
    int d = threadIdx.x;
    int icnt = g_icounts[k];
    long long ll = (long long)g_isums[k * DD + d];
    float s   = (float)((double)ll * FP_INV);
    float cnt = (float)icnt;
    float v   = __fdiv_rn(s, fmaxf(cnt, 1.0f));
    if (v == 0.0f) {
        int r = repl[iter * KK + k];
        v = X[(size_t)r * DD + d];
    }
    g_centers[k * DD + d] = v;
    g_isums[k * DD + d] = 0ULL;
    if (d == 0) g_icounts[k] = 0;

    float sq = __fmul_rn(v, v);
    #pragma unroll
    for (int o = 16; o > 0; o >>= 1) sq += __shfl_down_sync(0xffffffffu, sq, o);
    __shared__ float sh[2];
    if ((d & 31) == 0) sh[d >> 5] = sq;
    __syncthreads();
    if (d == 0) g_c2[k] = __fadd_rn(sh[0], sh[1]);
}

// ---------------- output: [assignments as float | centers] -----------------
__global__ void out_kernel(float* __restrict__ out) {
    int i = blockIdx.x * blockDim.x + threadIdx.x;
    if (i < NN) {
        out[i] = (float)g_assign[i];
    } else if (i < NN + KK * DD) {
        out[i] = g_centers[i - NN];
    }
}

// ---------------- launch ----------------------------------------------------
extern "C" void kernel_launch(void* const* d_in, const int* in_sizes, int n_in,
                              void* d_out, int out_size)
{
    const float* X    = nullptr;
    const float* C0   = nullptr;
    const int*   repl = nullptr;
    for (int i = 0; i < n_in; i++) {
        if (in_sizes[i] == NN * DD)       X    = (const float*)d_in[i];
        else if (in_sizes[i] == KK * DD)  C0   = (const float*)d_in[i];
        else if (in_sizes[i] == ITERS*KK) repl = (const int*)d_in[i];
    }
    float* out = (float*)d_out;

    prep_kernel<<<KK, DD>>>(C0);
    for (int i = 0; i < ITERS; i++) {
        assign_kernel<<<NN / RPB, 256>>>(X, C0, i);
        update_kernel<<<KK, DD>>>(X, repl, i);
    }
    int total = NN + KK * DD;
    out_kernel<<<(total + 255) / 256, 256>>>(out);
}